// round 11
// baseline (speedup 1.0000x reference)
#include <cuda_runtime.h>
#include <cstdint>

// Problem constants
#define NB 16
#define NG 64
#define NS 4096
#define NC 384
#define NH 6
#define ND 64

// fp32 helper-GEMM tile config (K1/K4, small)
#define BM 128
#define BN 64
#define BK 16
#define AP 132
#define BP2 68

// tf32 GEMM smem pitch
#define PA 20

// flag threshold coefficient (gap < TC * ||kp|| * max||q|| -> recompute)
#define TC 4.0e-3f

// Scratch
__device__ __align__(16) float g_qT[NB * NH * ND * NG];   // q^T: [bh][d][n]
__device__ int   g_idx[NB * NH * NS];
__device__ __align__(16) float g_acc[NB * NH * NG * ND];
__device__ int   g_cnt[NB * NH * NG];
__device__ float g_qmax[NB * NH];          // max_n ||q_n||^2 per bh (as float bits)
__device__ int   g_nflag;
__device__ int   g_flagged[NB * NH * NS];  // 1.5 MB worst case

// ---------------------------------------------------------------------------
// tf32 helpers
// ---------------------------------------------------------------------------
__device__ __forceinline__ uint32_t f2tf(float x) {
    uint32_t u;
    asm("cvt.rna.tf32.f32 %0, %1;" : "=r"(u) : "f"(x));
    return u;
}

__device__ __forceinline__ void mma_tf32(float c[4], const uint32_t a[4],
                                         const uint32_t b[2]) {
    asm volatile(
        "mma.sync.aligned.m16n8k8.row.col.f32.tf32.tf32.f32 "
        "{%0,%1,%2,%3}, {%4,%5,%6,%7}, {%8,%9}, {%0,%1,%2,%3};"
        : "+f"(c[0]), "+f"(c[1]), "+f"(c[2]), "+f"(c[3])
        : "r"(a[0]), "r"(a[1]), "r"(a[2]), "r"(a[3]), "r"(b[0]), "r"(b[1]));
}

template <bool SPLIT>
__device__ __forceinline__ void sts_split(float* hi, float* lo, int off, float4 v) {
    float x[4] = {v.x, v.y, v.z, v.w};
#pragma unroll
    for (int j = 0; j < 4; ++j) {
        uint32_t h = f2tf(x[j]);
        hi[off + j] = __uint_as_float(h);
        if (SPLIT)
            lo[off + j] = __uint_as_float(f2tf(x[j] - __uint_as_float(h)));
    }
}

// ---------------------------------------------------------------------------
// 128x64 block tile tf32 GEMM core (R3-proven, unpipelined).
// SPLIT=true: 3xTF32 (fp32-accurate). SPLIT=false: 1xTF32.
// ---------------------------------------------------------------------------
template <bool SPLIT>
__device__ __forceinline__ void gemm_tf32_128x64(
    const float* __restrict__ A, const float* __restrict__ W, int mBase,
    float c[2][4][4], float* sAh, float* sAl, float* sBh, float* sBl, int tid) {
    int lane = tid & 31;
    int warpM = (tid >> 5) & 3;
    int warpN = tid >> 7;
    int grp = lane >> 2, qd = lane & 3;

    int am0 = tid >> 2;            // 0..63
    int ak = (tid & 3) * 4;
    const float* pa0 = A + (size_t)(mBase + am0) * NC + ak;
    const float* pa1 = A + (size_t)(mBase + am0 + 64) * NC + ak;
    const float* pb  = W + (size_t)am0 * NC + ak;

    float4 ra0 = *(const float4*)pa0;
    float4 ra1 = *(const float4*)pa1;
    float4 rb  = *(const float4*)pb;

    for (int kt = 0; kt < NC / 16; ++kt) {
        __syncthreads();
        sts_split<SPLIT>(sAh, sAl, am0 * PA + ak, ra0);
        sts_split<SPLIT>(sAh, sAl, (am0 + 64) * PA + ak, ra1);
        sts_split<SPLIT>(sBh, sBl, am0 * PA + ak, rb);
        __syncthreads();
        if (kt < NC / 16 - 1) {
            int k0 = (kt + 1) * 16;
            ra0 = *(const float4*)(pa0 + k0);
            ra1 = *(const float4*)(pa1 + k0);
            rb  = *(const float4*)(pb + k0);
        }
#pragma unroll
        for (int kk = 0; kk < 16; kk += 8) {
            uint32_t ah[2][4], al[2][4], bhf[4][2], blf[4][2];
#pragma unroll
            for (int mi = 0; mi < 2; ++mi) {
                int r = warpM * 32 + mi * 16 + grp;
                const float* ph = sAh + r * PA + kk + qd;
                ah[mi][0] = __float_as_uint(ph[0]);
                ah[mi][1] = __float_as_uint(ph[8 * PA]);
                ah[mi][2] = __float_as_uint(ph[4]);
                ah[mi][3] = __float_as_uint(ph[8 * PA + 4]);
                if (SPLIT) {
                    const float* pl = sAl + r * PA + kk + qd;
                    al[mi][0] = __float_as_uint(pl[0]);
                    al[mi][1] = __float_as_uint(pl[8 * PA]);
                    al[mi][2] = __float_as_uint(pl[4]);
                    al[mi][3] = __float_as_uint(pl[8 * PA + 4]);
                }
            }
#pragma unroll
            for (int nj = 0; nj < 4; ++nj) {
                int cn = warpN * 32 + nj * 8 + grp;
                const float* pkh = sBh + cn * PA + kk + qd;
                bhf[nj][0] = __float_as_uint(pkh[0]);
                bhf[nj][1] = __float_as_uint(pkh[4]);
                if (SPLIT) {
                    const float* pkl = sBl + cn * PA + kk + qd;
                    blf[nj][0] = __float_as_uint(pkl[0]);
                    blf[nj][1] = __float_as_uint(pkl[4]);
                }
            }
#pragma unroll
            for (int mi = 0; mi < 2; ++mi)
#pragma unroll
                for (int nj = 0; nj < 4; ++nj) {
                    if (SPLIT) {
                        mma_tf32(c[mi][nj], al[mi], bhf[nj]);
                        mma_tf32(c[mi][nj], ah[mi], blf[nj]);
                    }
                    mma_tf32(c[mi][nj], ah[mi], bhf[nj]);
                }
        }
    }
}

// ---------------------------------------------------------------------------
// fp32 helper GEMM pieces (K1 / K4)
// ---------------------------------------------------------------------------
__device__ __forceinline__ void load_A_tile(const float* __restrict__ A,
                                            int mBase, int k0, float* As, int tid) {
#pragma unroll
    for (int l = 0; l < 2; ++l) {
        int lin = tid * 2 + l;
        int m = lin >> 2;
        int kg = (lin & 3) * 4;
        float4 v = *(const float4*)(A + (size_t)(mBase + m) * NC + k0 + kg);
        As[(kg + 0) * AP + m] = v.x;
        As[(kg + 1) * AP + m] = v.y;
        As[(kg + 2) * AP + m] = v.z;
        As[(kg + 3) * AP + m] = v.w;
    }
}

__device__ __forceinline__ void load_B_tile(const float* __restrict__ W,
                                            int nBase, int k0, float* Bs, int tid) {
    int wr = tid >> 2;
    int kg = (tid & 3) * 4;
    float4 v = *(const float4*)(W + (size_t)(nBase + wr) * NC + k0 + kg);
    Bs[(kg + 0) * BP2 + wr] = v.x;
    Bs[(kg + 1) * BP2 + wr] = v.y;
    Bs[(kg + 2) * BP2 + wr] = v.z;
    Bs[(kg + 3) * BP2 + wr] = v.w;
}

__device__ __forceinline__ void mma_tile(const float* As, const float* Bs,
                                         float c[8][4], int trow, int tcol) {
#pragma unroll
    for (int k = 0; k < BK; ++k) {
        float4 a0 = *(const float4*)(As + k * AP + trow * 8);
        float4 a1 = *(const float4*)(As + k * AP + trow * 8 + 4);
        float4 b0 = *(const float4*)(Bs + k * BP2 + tcol * 4);
        float a[8] = {a0.x, a0.y, a0.z, a0.w, a1.x, a1.y, a1.z, a1.w};
        float b[4] = {b0.x, b0.y, b0.z, b0.w};
#pragma unroll
        for (int i = 0; i < 8; ++i)
#pragma unroll
            for (int j = 0; j < 4; ++j)
                c[i][j] += a[i] * b[j];
    }
}

// ---------------------------------------------------------------------------
// K0: zero accumulators + flag state
// ---------------------------------------------------------------------------
__global__ void k_zero() {
    int i = blockIdx.x * blockDim.x + threadIdx.x;
    if (i < NB * NH * NG * ND) g_acc[i] = 0.0f;
    if (i < NB * NH * NG) g_cnt[i] = 0;
    if (i < NB * NH) g_qmax[i] = 0.0f;
    if (i == 0) g_nflag = 0;
}

// ---------------------------------------------------------------------------
// K1: q projection -> g_qT[bh][d][n], plus per-bh max ||q_n||^2
// ---------------------------------------------------------------------------
__global__ void __launch_bounds__(256) k_qproj(const float* __restrict__ query,
                                               const float* __restrict__ Wq) {
    __shared__ float As[BK * AP];
    __shared__ float Bs[BK * BP2];
    int tid = threadIdx.x;
    int trow = tid >> 4, tcol = tid & 15;
    int mBase = blockIdx.x * BM;
    int h = blockIdx.y;

    float c[8][4] = {};
    for (int k0 = 0; k0 < NC; k0 += BK) {
        load_A_tile(query, mBase, k0, As, tid);
        load_B_tile(Wq, h * 64, k0, Bs, tid);
        __syncthreads();
        mma_tile(As, Bs, c, trow, tcol);
        __syncthreads();
    }
#pragma unroll
    for (int i = 0; i < 8; ++i) {
        int m = mBase + trow * 8 + i;
        int b = m >> 6, n = m & 63;
        int bh = b * NH + h;
        float qn2 = 0.0f;
#pragma unroll
        for (int j = 0; j < 4; ++j) {
            int d = tcol * 4 + j;
            g_qT[((size_t)bh * ND + d) * NG + n] = c[i][j];
            qn2 += c[i][j] * c[i][j];
        }
        // reduce ||q_n||^2 over the 16 tcol lanes
#pragma unroll
        for (int off = 8; off >= 1; off >>= 1)
            qn2 += __shfl_xor_sync(0xffffffffu, qn2, off, 16);
        if (tcol == 0)
            atomicMax((unsigned int*)&g_qmax[bh], __float_as_uint(qn2));
    }
}

// ---------------------------------------------------------------------------
// K2: kp = key@Wk^T via 1xTF32 + fp32 score epilogue with top-2 margin test.
// Tokens whose top-2 gap < TC*||kp||*max||q|| are flagged for fp32 recompute.
// ---------------------------------------------------------------------------
__global__ void __launch_bounds__(256) k2_assign(const float* __restrict__ key,
                                                 const float* __restrict__ Wk) {
    __shared__ __align__(16) union {
        struct { float Ah[128 * PA]; float Bh[64 * PA]; } g;
        struct { float Kp[128 * 64]; float Qs[64 * 64]; } e;   // 48 KB
    } sm;

    int tid = threadIdx.x;
    int lane = tid & 31;
    int warpM = (tid >> 5) & 3, warpN = tid >> 7;
    int grp = lane >> 2, qd = lane & 3;

    int mBase = blockIdx.x * 128;
    int b = mBase >> 12;
    int sBase = mBase & (NS - 1);
    int h = blockIdx.y;
    int bh = b * NH + h;

    float cs[2][4][4] = {};
    gemm_tf32_128x64<false>(key, Wk + (size_t)h * 64 * NC, mBase, cs,
                            sm.g.Ah, nullptr, sm.g.Bh, nullptr, tid);

    __syncthreads();  // GEMM smem reads done before union repurpose

    // Stage kp accumulators to smem [s][d]
#pragma unroll
    for (int mi = 0; mi < 2; ++mi)
#pragma unroll
        for (int nj = 0; nj < 4; ++nj) {
            int row = warpM * 32 + mi * 16 + grp;
            int col = warpN * 32 + nj * 8 + 2 * qd;
            *(float2*)&sm.e.Kp[row * 64 + col] =
                make_float2(cs[mi][nj][0], cs[mi][nj][1]);
            *(float2*)&sm.e.Kp[(row + 8) * 64 + col] =
                make_float2(cs[mi][nj][2], cs[mi][nj][3]);
        }
    // Load q^T tile [d][n]
    {
        const float* qsrc = g_qT + (size_t)bh * ND * NG;
#pragma unroll
        for (int r = 0; r < 4; ++r) {
            int off = (tid + 256 * r) * 4;
            *(float4*)&sm.e.Qs[off] = *(const float4*)&qsrc[off];
        }
    }
    __syncthreads();

    float qmax = sqrtf(g_qmax[bh]);

    // scores[128 s][64 n] in fp32 + ||kp_s||^2
    int tr = tid >> 4, tc = tid & 15;
    float acc2[8][4] = {};
    float akk[8] = {};
#pragma unroll 8
    for (int d = 0; d < 64; ++d) {
        float4 q4 = *(const float4*)&sm.e.Qs[d * 64 + tc * 4];
#pragma unroll
        for (int i = 0; i < 8; ++i) {
            float a = sm.e.Kp[(tr * 8 + i) * 64 + d];
            acc2[i][0] += a * q4.x;
            acc2[i][1] += a * q4.y;
            acc2[i][2] += a * q4.z;
            acc2[i][3] += a * q4.w;
            akk[i] += a * a;
        }
    }
#pragma unroll
    for (int i = 0; i < 8; ++i) {
        // local top-2 of my 4 candidates
        float m1 = acc2[i][0], m2 = -3.4e38f;
        int i1 = tc * 4;
#pragma unroll
        for (int j = 1; j < 4; ++j) {
            float v = acc2[i][j];
            if (v > m1) { m2 = m1; m1 = v; i1 = tc * 4 + j; }
            else if (v > m2) m2 = v;
        }
        // 16-lane top-2 reduce
#pragma unroll
        for (int off = 8; off >= 1; off >>= 1) {
            float om1 = __shfl_down_sync(0xffffffffu, m1, off, 16);
            int   oi1 = __shfl_down_sync(0xffffffffu, i1, off, 16);
            float om2 = __shfl_down_sync(0xffffffffu, m2, off, 16);
            if (om1 > m1) {
                m2 = fmaxf(m1, om2); m1 = om1; i1 = oi1;
            } else {
                m2 = fmaxf(m2, fmaxf(om1, -3.4e38f));
            }
        }
        if (tc == 0) {
            int tok = bh * NS + sBase + tr * 8 + i;
            g_idx[tok] = i1;
            atomicAdd(&g_cnt[bh * NG + i1], 1);
            float T = TC * sqrtf(akk[i]) * qmax;
            if (m1 - m2 < T) {
                int p = atomicAdd(&g_nflag, 1);
                g_flagged[p] = tok;
            }
        }
    }
}

// ---------------------------------------------------------------------------
// K2b: exact fp32 recompute of flagged tokens; repairs g_idx / g_cnt
// one warp per token; fixed grid, strided over dynamic count
// ---------------------------------------------------------------------------
__global__ void __launch_bounds__(256) k_recompute(const float* __restrict__ key,
                                                   const float* __restrict__ Wk) {
    __shared__ float skey[8][NC];
    __shared__ float skp[8][64];
    int wid = threadIdx.x >> 5, lane = threadIdx.x & 31;
    int nf = g_nflag;

    for (int it = blockIdx.x * 8 + wid; it < nf; it += gridDim.x * 8) {
        int t = g_flagged[it];
        int bh = t >> 12, s = t & (NS - 1);
        int b = bh / NH, h = bh % NH;
        const float* kr = key + ((size_t)b * NS + s) * NC;
        for (int c4 = lane; c4 < NC / 4; c4 += 32)
            ((float4*)skey[wid])[c4] = ((const float4*)kr)[c4];
        __syncwarp();

#pragma unroll
        for (int half = 0; half < 2; ++half) {
            int d = half * 32 + lane;
            const float* wr = Wk + (size_t)(h * 64 + d) * NC;
            float acc = 0.0f;
            for (int c = 0; c < NC; c += 4) {
                float4 w4 = *(const float4*)(wr + c);
                acc += skey[wid][c] * w4.x;
                acc += skey[wid][c + 1] * w4.y;
                acc += skey[wid][c + 2] * w4.z;
                acc += skey[wid][c + 3] * w4.w;
            }
            skp[wid][d] = acc;
        }
        __syncwarp();

        const float* qb = g_qT + (size_t)bh * ND * NG;
        float best = -3.4e38f;
        int bi = 0;
#pragma unroll
        for (int half = 0; half < 2; ++half) {
            int n = half * 32 + lane;
            float sacc = 0.0f;
            for (int d = 0; d < 64; ++d)
                sacc += skp[wid][d] * qb[d * NG + n];
            if (sacc > best) { best = sacc; bi = n; }
        }
#pragma unroll
        for (int off = 16; off >= 1; off >>= 1) {
            float ov = __shfl_down_sync(0xffffffffu, best, off);
            int   oi = __shfl_down_sync(0xffffffffu, bi, off);
            if (ov > best || (ov == best && oi < bi)) { best = ov; bi = oi; }
        }
        if (lane == 0) {
            int old = g_idx[t];
            if (old != bi) {
                g_idx[t] = bi;
                atomicAdd(&g_cnt[bh * NG + old], -1);
                atomicAdd(&g_cnt[bh * NG + bi], 1);
            }
        }
        __syncwarp();
    }
}

// ---------------------------------------------------------------------------
// K3: vp = key@Wv^T via 1xTF32 + fused atomic scatter (R3-identical)
// ---------------------------------------------------------------------------
__global__ void __launch_bounds__(256) k3_scatter(const float* __restrict__ key,
                                                  const float* __restrict__ Wv) {
    __shared__ __align__(16) float Ah[128 * PA];
    __shared__ __align__(16) float Bvh[64 * PA];

    int tid = threadIdx.x;
    int lane = tid & 31;
    int warpM = (tid >> 5) & 3, warpN = tid >> 7;
    int grp = lane >> 2, qd = lane & 3;

    int mBase = blockIdx.x * 128;
    int b = mBase >> 12;
    int sBase = mBase & (NS - 1);
    int h = blockIdx.y;
    int bh = b * NH + h;

    float cv[2][4][4] = {};
    gemm_tf32_128x64<false>(key, Wv + (size_t)h * 64 * NC, mBase, cv,
                            Ah, nullptr, Bvh, nullptr, tid);

#pragma unroll
    for (int mi = 0; mi < 2; ++mi) {
        int s0 = sBase + warpM * 32 + mi * 16 + grp;
        int n0 = g_idx[bh * NS + s0];
        int n1 = g_idx[bh * NS + s0 + 8];
#pragma unroll
        for (int nj = 0; nj < 4; ++nj) {
            int d = warpN * 32 + nj * 8 + 2 * qd;
            float* p0 = &g_acc[(bh * NG + n0) * ND + d];
            atomicAdd(p0,     cv[mi][nj][0]);
            atomicAdd(p0 + 1, cv[mi][nj][1]);
            float* p1 = &g_acc[(bh * NG + n1) * ND + d];
            atomicAdd(p1,     cv[mi][nj][2]);
            atomicAdd(p1 + 1, cv[mi][nj][3]);
        }
    }
}

// ---------------------------------------------------------------------------
// K4: normalize + out = tmp @ Wp^T + bp
// ---------------------------------------------------------------------------
__global__ void __launch_bounds__(256) k_finalize(const float* __restrict__ Wp,
                                                  const float* __restrict__ bp,
                                                  float* __restrict__ out) {
    __shared__ float As[BK * AP];
    __shared__ float Bs[BK * BP2];
    int tid = threadIdx.x;
    int trow = tid >> 4, tcol = tid & 15;
    int mBase = blockIdx.x * BM;
    int nBase = blockIdx.y * BN;

    float c[8][4] = {};
    for (int k0 = 0; k0 < NC; k0 += BK) {
#pragma unroll
        for (int l = 0; l < 2; ++l) {
            int lin = tid * 2 + l;
            int m = lin >> 2;
            int kg = (lin & 3) * 4;
            int gm = mBase + m;
            int b = gm >> 6, n = gm & 63;
            int cc = k0 + kg;
            int h = cc >> 6, d = cc & 63;
            int bh = b * NH + h;
            float inv = 1.0f / (float)(g_cnt[bh * NG + n] + 1);
            float4 v = *(const float4*)&g_acc[(bh * NG + n) * ND + d];
            As[(kg + 0) * AP + m] = v.x * inv;
            As[(kg + 1) * AP + m] = v.y * inv;
            As[(kg + 2) * AP + m] = v.z * inv;
            As[(kg + 3) * AP + m] = v.w * inv;
        }
        load_B_tile(Wp, nBase, k0, Bs, tid);
        __syncthreads();
        mma_tile(As, Bs, c, trow, tcol);
        __syncthreads();
    }

    float4 bias = *(const float4*)&bp[nBase + tcol * 4];
#pragma unroll
    for (int i = 0; i < 8; ++i) {
        int m = mBase + trow * 8 + i;
        float4 v = make_float4(c[i][0] + bias.x, c[i][1] + bias.y,
                               c[i][2] + bias.z, c[i][3] + bias.w);
        *(float4*)&out[(size_t)m * NC + nBase + tcol * 4] = v;
    }
}

// ---------------------------------------------------------------------------
extern "C" void kernel_launch(void* const* d_in, const int* in_sizes, int n_in,
                              void* d_out, int out_size) {
    const float* query = (const float*)d_in[0];
    const float* key   = (const float*)d_in[1];
    const float* Wq    = (const float*)d_in[2];
    const float* Wk    = (const float*)d_in[3];
    const float* Wv    = (const float*)d_in[4];
    const float* Wp    = (const float*)d_in[5];
    const float* bp    = (const float*)d_in[6];
    float* out = (float*)d_out;

    k_zero<<<(NB * NH * NG * ND + 255) / 256, 256>>>();
    k_qproj<<<dim3(8, 6), 256>>>(query, Wq);
    k2_assign<<<dim3((NB * NS) / 128, NH), 256>>>(key, Wk);
    k_recompute<<<148, 256>>>(key, Wk);
    k3_scatter<<<dim3((NB * NS) / 128, NH), 256>>>(key, Wv);
    k_finalize<<<dim3(8, 6), 256>>>(Wp, bp, out);
}

// round 13
// speedup vs baseline: 1.9552x; 1.9552x over previous
#include <cuda_runtime.h>
#include <cstdint>

// Problem constants
#define NB 16
#define NG 64
#define NS 4096
#define NC 384
#define NH 6
#define ND 64

// fp32 helper-GEMM tile config (K1/K4, small)
#define BM 128
#define BN 64
#define BK 16
#define AP 132
#define BP2 68

// tf32 GEMM smem pitch
#define PA 20

// repair GEMM smem pitch (floats; 36*4=144 B keeps float4 rows 16B-aligned)
#define RP 36

// flag threshold coefficient (gap < TC * ||kp|| * max||q|| -> recompute)
#define TC 2.0e-3f

// Scratch
__device__ __align__(16) float g_qT[NB * NH * ND * NG];   // q^T: [bh][d][n]
__device__ int   g_idx[NB * NH * NS];
__device__ __align__(16) float g_acc[NB * NH * NG * ND];
__device__ int   g_cnt[NB * NH * NG];
__device__ float g_qmax[NB * NH];
__device__ int   g_fcnt[NB * NH];
__device__ int   g_flag[NB * NH * NS];     // per-bh buckets of flagged s

// ---------------------------------------------------------------------------
// tf32 helpers
// ---------------------------------------------------------------------------
__device__ __forceinline__ uint32_t f2tf(float x) {
    uint32_t u;
    asm("cvt.rna.tf32.f32 %0, %1;" : "=r"(u) : "f"(x));
    return u;
}

__device__ __forceinline__ void mma_tf32(float c[4], const uint32_t a[4],
                                         const uint32_t b[2]) {
    asm volatile(
        "mma.sync.aligned.m16n8k8.row.col.f32.tf32.tf32.f32 "
        "{%0,%1,%2,%3}, {%4,%5,%6,%7}, {%8,%9}, {%0,%1,%2,%3};"
        : "+f"(c[0]), "+f"(c[1]), "+f"(c[2]), "+f"(c[3])
        : "r"(a[0]), "r"(a[1]), "r"(a[2]), "r"(a[3]), "r"(b[0]), "r"(b[1]));
}

__device__ __forceinline__ void sts_cvt(float* hi, int off, float4 v) {
    hi[off + 0] = __uint_as_float(f2tf(v.x));
    hi[off + 1] = __uint_as_float(f2tf(v.y));
    hi[off + 2] = __uint_as_float(f2tf(v.z));
    hi[off + 3] = __uint_as_float(f2tf(v.w));
}

// ---------------------------------------------------------------------------
// 128x64 block tile 1xTF32 GEMM core (R3/R11-proven)
// ---------------------------------------------------------------------------
__device__ __forceinline__ void gemm_tf32_1x(
    const float* __restrict__ A, const float* __restrict__ W, int mBase,
    float c[2][4][4], float* sAh, float* sBh, int tid) {
    int lane = tid & 31;
    int warpM = (tid >> 5) & 3;
    int warpN = tid >> 7;
    int grp = lane >> 2, qd = lane & 3;

    int am0 = tid >> 2;
    int ak = (tid & 3) * 4;
    const float* pa0 = A + (size_t)(mBase + am0) * NC + ak;
    const float* pa1 = A + (size_t)(mBase + am0 + 64) * NC + ak;
    const float* pb  = W + (size_t)am0 * NC + ak;

    float4 ra0 = *(const float4*)pa0;
    float4 ra1 = *(const float4*)pa1;
    float4 rb  = *(const float4*)pb;

    for (int kt = 0; kt < NC / 16; ++kt) {
        __syncthreads();
        sts_cvt(sAh, am0 * PA + ak, ra0);
        sts_cvt(sAh, (am0 + 64) * PA + ak, ra1);
        sts_cvt(sBh, am0 * PA + ak, rb);
        __syncthreads();
        if (kt < NC / 16 - 1) {
            int k0 = (kt + 1) * 16;
            ra0 = *(const float4*)(pa0 + k0);
            ra1 = *(const float4*)(pa1 + k0);
            rb  = *(const float4*)(pb + k0);
        }
#pragma unroll
        for (int kk = 0; kk < 16; kk += 8) {
            uint32_t ah[2][4], bhf[4][2];
#pragma unroll
            for (int mi = 0; mi < 2; ++mi) {
                int r = warpM * 32 + mi * 16 + grp;
                const float* ph = sAh + r * PA + kk + qd;
                ah[mi][0] = __float_as_uint(ph[0]);
                ah[mi][1] = __float_as_uint(ph[8 * PA]);
                ah[mi][2] = __float_as_uint(ph[4]);
                ah[mi][3] = __float_as_uint(ph[8 * PA + 4]);
            }
#pragma unroll
            for (int nj = 0; nj < 4; ++nj) {
                int cn = warpN * 32 + nj * 8 + grp;
                const float* pkh = sBh + cn * PA + kk + qd;
                bhf[nj][0] = __float_as_uint(pkh[0]);
                bhf[nj][1] = __float_as_uint(pkh[4]);
            }
#pragma unroll
            for (int mi = 0; mi < 2; ++mi)
#pragma unroll
                for (int nj = 0; nj < 4; ++nj)
                    mma_tf32(c[mi][nj], ah[mi], bhf[nj]);
        }
    }
}

// ---------------------------------------------------------------------------
// fp32 helper GEMM pieces (K1 / K4)
// ---------------------------------------------------------------------------
__device__ __forceinline__ void load_A_tile(const float* __restrict__ A,
                                            int mBase, int k0, float* As, int tid) {
#pragma unroll
    for (int l = 0; l < 2; ++l) {
        int lin = tid * 2 + l;
        int m = lin >> 2;
        int kg = (lin & 3) * 4;
        float4 v = *(const float4*)(A + (size_t)(mBase + m) * NC + k0 + kg);
        As[(kg + 0) * AP + m] = v.x;
        As[(kg + 1) * AP + m] = v.y;
        As[(kg + 2) * AP + m] = v.z;
        As[(kg + 3) * AP + m] = v.w;
    }
}

__device__ __forceinline__ void load_B_tile(const float* __restrict__ W,
                                            int nBase, int k0, float* Bs, int tid) {
    int wr = tid >> 2;
    int kg = (tid & 3) * 4;
    float4 v = *(const float4*)(W + (size_t)(nBase + wr) * NC + k0 + kg);
    Bs[(kg + 0) * BP2 + wr] = v.x;
    Bs[(kg + 1) * BP2 + wr] = v.y;
    Bs[(kg + 2) * BP2 + wr] = v.z;
    Bs[(kg + 3) * BP2 + wr] = v.w;
}

__device__ __forceinline__ void mma_tile(const float* As, const float* Bs,
                                         float c[8][4], int trow, int tcol) {
#pragma unroll
    for (int k = 0; k < BK; ++k) {
        float4 a0 = *(const float4*)(As + k * AP + trow * 8);
        float4 a1 = *(const float4*)(As + k * AP + trow * 8 + 4);
        float4 b0 = *(const float4*)(Bs + k * BP2 + tcol * 4);
        float a[8] = {a0.x, a0.y, a0.z, a0.w, a1.x, a1.y, a1.z, a1.w};
        float b[4] = {b0.x, b0.y, b0.z, b0.w};
#pragma unroll
        for (int i = 0; i < 8; ++i)
#pragma unroll
            for (int j = 0; j < 4; ++j)
                c[i][j] += a[i] * b[j];
    }
}

// ---------------------------------------------------------------------------
// K0: zero accumulators + flag state
// ---------------------------------------------------------------------------
__global__ void k_zero() {
    int i = blockIdx.x * blockDim.x + threadIdx.x;
    if (i < NB * NH * NG * ND) g_acc[i] = 0.0f;
    if (i < NB * NH * NG) g_cnt[i] = 0;
    if (i < NB * NH) { g_qmax[i] = 0.0f; g_fcnt[i] = 0; }
}

// ---------------------------------------------------------------------------
// K1: q projection -> g_qT[bh][d][n], plus per-bh max ||q_n||^2
// ---------------------------------------------------------------------------
__global__ void __launch_bounds__(256) k_qproj(const float* __restrict__ query,
                                               const float* __restrict__ Wq) {
    __shared__ float As[BK * AP];
    __shared__ float Bs[BK * BP2];
    int tid = threadIdx.x;
    int trow = tid >> 4, tcol = tid & 15;
    int mBase = blockIdx.x * BM;
    int h = blockIdx.y;

    float c[8][4] = {};
    for (int k0 = 0; k0 < NC; k0 += BK) {
        load_A_tile(query, mBase, k0, As, tid);
        load_B_tile(Wq, h * 64, k0, Bs, tid);
        __syncthreads();
        mma_tile(As, Bs, c, trow, tcol);
        __syncthreads();
    }
#pragma unroll
    for (int i = 0; i < 8; ++i) {
        int m = mBase + trow * 8 + i;
        int b = m >> 6, n = m & 63;
        int bh = b * NH + h;
        float qn2 = 0.0f;
#pragma unroll
        for (int j = 0; j < 4; ++j) {
            int d = tcol * 4 + j;
            g_qT[((size_t)bh * ND + d) * NG + n] = c[i][j];
            qn2 += c[i][j] * c[i][j];
        }
#pragma unroll
        for (int off = 8; off >= 1; off >>= 1)
            qn2 += __shfl_xor_sync(0xffffffffu, qn2, off, 16);
        if (tcol == 0)
            atomicMax((unsigned int*)&g_qmax[bh], __float_as_uint(qn2));
    }
}

// ---------------------------------------------------------------------------
// K2: kp = key@Wk^T via 1xTF32 + fp32 score epilogue with top-2 margin test
// ---------------------------------------------------------------------------
__global__ void __launch_bounds__(256) k2_assign(const float* __restrict__ key,
                                                 const float* __restrict__ Wk) {
    __shared__ __align__(16) union {
        struct { float Ah[128 * PA]; float Bh[64 * PA]; } g;
        struct { float Kp[128 * 64]; float Qs[64 * 64]; } e;   // 48 KB
    } sm;

    int tid = threadIdx.x;
    int lane = tid & 31;
    int warpM = (tid >> 5) & 3, warpN = tid >> 7;
    int grp = lane >> 2, qd = lane & 3;

    int mBase = blockIdx.x * 128;
    int b = mBase >> 12;
    int sBase = mBase & (NS - 1);
    int h = blockIdx.y;
    int bh = b * NH + h;

    float cs[2][4][4] = {};
    gemm_tf32_1x(key, Wk + (size_t)h * 64 * NC, mBase, cs,
                 sm.g.Ah, sm.g.Bh, tid);

    __syncthreads();

#pragma unroll
    for (int mi = 0; mi < 2; ++mi)
#pragma unroll
        for (int nj = 0; nj < 4; ++nj) {
            int row = warpM * 32 + mi * 16 + grp;
            int col = warpN * 32 + nj * 8 + 2 * qd;
            *(float2*)&sm.e.Kp[row * 64 + col] =
                make_float2(cs[mi][nj][0], cs[mi][nj][1]);
            *(float2*)&sm.e.Kp[(row + 8) * 64 + col] =
                make_float2(cs[mi][nj][2], cs[mi][nj][3]);
        }
    {
        const float* qsrc = g_qT + (size_t)bh * ND * NG;
#pragma unroll
        for (int r = 0; r < 4; ++r) {
            int off = (tid + 256 * r) * 4;
            *(float4*)&sm.e.Qs[off] = *(const float4*)&qsrc[off];
        }
    }
    __syncthreads();

    float qmax = sqrtf(g_qmax[bh]);

    int tr = tid >> 4, tc = tid & 15;
    float acc2[8][4] = {};
    float akk[8] = {};
#pragma unroll 8
    for (int d = 0; d < 64; ++d) {
        float4 q4 = *(const float4*)&sm.e.Qs[d * 64 + tc * 4];
#pragma unroll
        for (int i = 0; i < 8; ++i) {
            float a = sm.e.Kp[(tr * 8 + i) * 64 + d];
            acc2[i][0] += a * q4.x;
            acc2[i][1] += a * q4.y;
            acc2[i][2] += a * q4.z;
            acc2[i][3] += a * q4.w;
            akk[i] += a * a;
        }
    }
#pragma unroll
    for (int i = 0; i < 8; ++i) {
        float m1 = acc2[i][0], m2 = -3.4e38f;
        int i1 = tc * 4;
#pragma unroll
        for (int j = 1; j < 4; ++j) {
            float v = acc2[i][j];
            if (v > m1) { m2 = m1; m1 = v; i1 = tc * 4 + j; }
            else if (v > m2) m2 = v;
        }
#pragma unroll
        for (int off = 8; off >= 1; off >>= 1) {
            float om1 = __shfl_down_sync(0xffffffffu, m1, off, 16);
            int   oi1 = __shfl_down_sync(0xffffffffu, i1, off, 16);
            float om2 = __shfl_down_sync(0xffffffffu, m2, off, 16);
            if (om1 > m1) { m2 = fmaxf(m1, om2); m1 = om1; i1 = oi1; }
            else          { m2 = fmaxf(m2, om1); }
        }
        if (tc == 0) {
            int s = sBase + tr * 8 + i;
            g_idx[bh * NS + s] = i1;
            atomicAdd(&g_cnt[bh * NG + i1], 1);
            float T = TC * sqrtf(akk[i]) * qmax;
            if (m1 - m2 < T) {
                int p = atomicAdd(&g_fcnt[bh], 1);
                g_flag[bh * NS + p] = s;
            }
        }
    }
}

// ---------------------------------------------------------------------------
// K2b: batched fp32 recompute of flagged tokens (per-bh mini-GEMM)
// grid = 96 blocks (one per bh), 256 threads, chunks of 64 tokens
// ---------------------------------------------------------------------------
__global__ void __launch_bounds__(256) k_repair(const float* __restrict__ key,
                                                const float* __restrict__ Wk) {
    __shared__ __align__(16) union {
        struct { float A[64 * RP]; float B[64 * RP]; } g;  // 18432 B
        float Q[64 * 64];                                  // 16384 B
    } u;
    __shared__ __align__(16) float Kp[64 * 68];
    __shared__ int sS[64];

    int tid = threadIdx.x;
    int bh = blockIdx.x;
    int b = bh / NH, h = bh % NH;
    int nf = g_fcnt[bh];
    const float* qsrc = g_qT + (size_t)bh * ND * NG;

    int ttr = tid >> 4, ttc = tid & 15;
    int lr = tid >> 2;              // 0..63
    int cg = (tid & 3) * 8;         // 0,8,16,24
    const float* wrow = Wk + (size_t)(h * 64 + lr) * NC + cg;

    for (int c0 = 0; c0 < nf; c0 += 64) {
        __syncthreads();
        if (tid < 64) {
            int i = c0 + tid;
            sS[tid] = g_flag[bh * NS + (i < nf ? i : nf - 1)];
        }
        __syncthreads();

        float acc[4][4] = {};
        const float* krow = key + ((size_t)b * NS + sS[lr]) * NC + cg;
        for (int kt = 0; kt < NC / 32; ++kt) {
            int kof = kt * 32;
            *(float4*)&u.g.A[lr * RP + cg]     = *(const float4*)(krow + kof);
            *(float4*)&u.g.A[lr * RP + cg + 4] = *(const float4*)(krow + kof + 4);
            *(float4*)&u.g.B[lr * RP + cg]     = *(const float4*)(wrow + kof);
            *(float4*)&u.g.B[lr * RP + cg + 4] = *(const float4*)(wrow + kof + 4);
            __syncthreads();
#pragma unroll 8
            for (int c = 0; c < 32; ++c) {
                float a[4], bb[4];
#pragma unroll
                for (int i = 0; i < 4; ++i) a[i] = u.g.A[(ttr * 4 + i) * RP + c];
#pragma unroll
                for (int j = 0; j < 4; ++j) bb[j] = u.g.B[(ttc * 4 + j) * RP + c];
#pragma unroll
                for (int i = 0; i < 4; ++i)
#pragma unroll
                    for (int j = 0; j < 4; ++j)
                        acc[i][j] += a[i] * bb[j];
            }
            __syncthreads();
        }
        // kp -> smem, then q tile (overwrites A/B)
#pragma unroll
        for (int i = 0; i < 4; ++i)
#pragma unroll
            for (int j = 0; j < 4; ++j)
                Kp[(ttr * 4 + i) * 68 + ttc * 4 + j] = acc[i][j];
#pragma unroll
        for (int r = 0; r < 4; ++r) {
            int off = (tid + 256 * r) * 4;
            *(float4*)&u.Q[off] = *(const float4*)&qsrc[off];
        }
        __syncthreads();

        // fp32 scores + argmax (reference association: dot over d ascending)
        float s2[4][4] = {};
#pragma unroll 8
        for (int d = 0; d < 64; ++d) {
            float4 q4 = *(const float4*)&u.Q[d * 64 + ttc * 4];
#pragma unroll
            for (int i = 0; i < 4; ++i) {
                float a = Kp[(ttr * 4 + i) * 68 + d];
                s2[i][0] += a * q4.x;
                s2[i][1] += a * q4.y;
                s2[i][2] += a * q4.z;
                s2[i][3] += a * q4.w;
            }
        }
#pragma unroll
        for (int i = 0; i < 4; ++i) {
            float mv = s2[i][0];
            int mi = ttc * 4;
#pragma unroll
            for (int j = 1; j < 4; ++j)
                if (s2[i][j] > mv) { mv = s2[i][j]; mi = ttc * 4 + j; }
#pragma unroll
            for (int off = 8; off >= 1; off >>= 1) {
                float ov = __shfl_down_sync(0xffffffffu, mv, off, 16);
                int   oi = __shfl_down_sync(0xffffffffu, mi, off, 16);
                if (ov > mv || (ov == mv && oi < mi)) { mv = ov; mi = oi; }
            }
            int row = ttr * 4 + i;
            if (ttc == 0 && c0 + row < nf) {
                int s = sS[row];
                int old = g_idx[bh * NS + s];
                if (old != mi) {
                    g_idx[bh * NS + s] = mi;
                    atomicAdd(&g_cnt[bh * NG + old], -1);
                    atomicAdd(&g_cnt[bh * NG + mi], 1);
                }
            }
        }
    }
}

// ---------------------------------------------------------------------------
// K3: vp = key@Wv^T via 1xTF32 + fused atomic scatter (R3-identical)
// ---------------------------------------------------------------------------
__global__ void __launch_bounds__(256) k3_scatter(const float* __restrict__ key,
                                                  const float* __restrict__ Wv) {
    __shared__ __align__(16) float Ah[128 * PA];
    __shared__ __align__(16) float Bvh[64 * PA];

    int tid = threadIdx.x;
    int lane = tid & 31;
    int warpM = (tid >> 5) & 3, warpN = tid >> 7;
    int grp = lane >> 2, qd = lane & 3;

    int mBase = blockIdx.x * 128;
    int b = mBase >> 12;
    int sBase = mBase & (NS - 1);
    int h = blockIdx.y;
    int bh = b * NH + h;

    float cv[2][4][4] = {};
    gemm_tf32_1x(key, Wv + (size_t)h * 64 * NC, mBase, cv, Ah, Bvh, tid);

#pragma unroll
    for (int mi = 0; mi < 2; ++mi) {
        int s0 = sBase + warpM * 32 + mi * 16 + grp;
        int n0 = g_idx[bh * NS + s0];
        int n1 = g_idx[bh * NS + s0 + 8];
#pragma unroll
        for (int nj = 0; nj < 4; ++nj) {
            int d = warpN * 32 + nj * 8 + 2 * qd;
            float* p0 = &g_acc[(bh * NG + n0) * ND + d];
            atomicAdd(p0,     cv[mi][nj][0]);
            atomicAdd(p0 + 1, cv[mi][nj][1]);
            float* p1 = &g_acc[(bh * NG + n1) * ND + d];
            atomicAdd(p1,     cv[mi][nj][2]);
            atomicAdd(p1 + 1, cv[mi][nj][3]);
        }
    }
}

// ---------------------------------------------------------------------------
// K4: normalize + out = tmp @ Wp^T + bp
// ---------------------------------------------------------------------------
__global__ void __launch_bounds__(256) k_finalize(const float* __restrict__ Wp,
                                                  const float* __restrict__ bp,
                                                  float* __restrict__ out) {
    __shared__ float As[BK * AP];
    __shared__ float Bs[BK * BP2];
    int tid = threadIdx.x;
    int trow = tid >> 4, tcol = tid & 15;
    int mBase = blockIdx.x * BM;
    int nBase = blockIdx.y * BN;

    float c[8][4] = {};
    for (int k0 = 0; k0 < NC; k0 += BK) {
#pragma unroll
        for (int l = 0; l < 2; ++l) {
            int lin = tid * 2 + l;
            int m = lin >> 2;
            int kg = (lin & 3) * 4;
            int gm = mBase + m;
            int b = gm >> 6, n = gm & 63;
            int cc = k0 + kg;
            int h = cc >> 6, d = cc & 63;
            int bh = b * NH + h;
            float inv = 1.0f / (float)(g_cnt[bh * NG + n] + 1);
            float4 v = *(const float4*)&g_acc[(bh * NG + n) * ND + d];
            As[(kg + 0) * AP + m] = v.x * inv;
            As[(kg + 1) * AP + m] = v.y * inv;
            As[(kg + 2) * AP + m] = v.z * inv;
            As[(kg + 3) * AP + m] = v.w * inv;
        }
        load_B_tile(Wp, nBase, k0, Bs, tid);
        __syncthreads();
        mma_tile(As, Bs, c, trow, tcol);
        __syncthreads();
    }

    float4 bias = *(const float4*)&bp[nBase + tcol * 4];
#pragma unroll
    for (int i = 0; i < 8; ++i) {
        int m = mBase + trow * 8 + i;
        float4 v = make_float4(c[i][0] + bias.x, c[i][1] + bias.y,
                               c[i][2] + bias.z, c[i][3] + bias.w);
        *(float4*)&out[(size_t)m * NC + nBase + tcol * 4] = v;
    }
}

// ---------------------------------------------------------------------------
extern "C" void kernel_launch(void* const* d_in, const int* in_sizes, int n_in,
                              void* d_out, int out_size) {
    const float* query = (const float*)d_in[0];
    const float* key   = (const float*)d_in[1];
    const float* Wq    = (const float*)d_in[2];
    const float* Wk    = (const float*)d_in[3];
    const float* Wv    = (const float*)d_in[4];
    const float* Wp    = (const float*)d_in[5];
    const float* bp    = (const float*)d_in[6];
    float* out = (float*)d_out;

    k_zero<<<(NB * NH * NG * ND + 255) / 256, 256>>>();
    k_qproj<<<dim3(8, 6), 256>>>(query, Wq);
    k2_assign<<<dim3((NB * NS) / 128, NH), 256>>>(key, Wk);
    k_repair<<<NB * NH, 256>>>(key, Wk);
    k3_scatter<<<dim3((NB * NS) / 128, NH), 256>>>(key, Wv);
    k_finalize<<<dim3(8, 6), 256>>>(Wp, bp, out);
}

// round 14
// speedup vs baseline: 2.1352x; 1.0920x over previous
#include <cuda_runtime.h>
#include <cstdint>

// Problem constants
#define NB 16
#define NG 64
#define NS 4096
#define NC 384
#define NH 6
#define ND 64

// fp32 helper-GEMM tile config (K1/K4, small)
#define BM 128
#define BN 64
#define BK 16
#define AP 132
#define BP2 68

// tf32 GEMM smem pitch
#define PA 20

// repair GEMM smem pitch (floats; 36*4=144 B keeps float4 rows 16B-aligned)
#define RP 36
// repair parallelism: chunk-slices per bucket
#define RSPLIT 8

// flag threshold coefficient (gap < TC * ||kp|| * max||q|| -> recompute)
#define TC 2.0e-3f

// Scratch
__device__ __align__(16) float g_qT[NB * NH * ND * NG];   // q^T: [bh][d][n]
__device__ int   g_idx[NB * NH * NS];
__device__ __align__(16) float g_acc[NB * NH * NG * ND];
__device__ int   g_cnt[NB * NH * NG];
__device__ float g_qmax[NB * NH];
__device__ int   g_fcnt[NB * NH];
__device__ int   g_flag[NB * NH * NS];     // per-bh buckets of flagged s

// ---------------------------------------------------------------------------
// tf32 helpers
// ---------------------------------------------------------------------------
__device__ __forceinline__ uint32_t f2tf(float x) {
    uint32_t u;
    asm("cvt.rna.tf32.f32 %0, %1;" : "=r"(u) : "f"(x));
    return u;
}

__device__ __forceinline__ void mma_tf32(float c[4], const uint32_t a[4],
                                         const uint32_t b[2]) {
    asm volatile(
        "mma.sync.aligned.m16n8k8.row.col.f32.tf32.tf32.f32 "
        "{%0,%1,%2,%3}, {%4,%5,%6,%7}, {%8,%9}, {%0,%1,%2,%3};"
        : "+f"(c[0]), "+f"(c[1]), "+f"(c[2]), "+f"(c[3])
        : "r"(a[0]), "r"(a[1]), "r"(a[2]), "r"(a[3]), "r"(b[0]), "r"(b[1]));
}

__device__ __forceinline__ void sts_cvt(float* hi, int off, float4 v) {
    hi[off + 0] = __uint_as_float(f2tf(v.x));
    hi[off + 1] = __uint_as_float(f2tf(v.y));
    hi[off + 2] = __uint_as_float(f2tf(v.z));
    hi[off + 3] = __uint_as_float(f2tf(v.w));
}

// ---------------------------------------------------------------------------
// 128x64 block tile 1xTF32 GEMM core (R3/R11-proven)
// ---------------------------------------------------------------------------
__device__ __forceinline__ void gemm_tf32_1x(
    const float* __restrict__ A, const float* __restrict__ W, int mBase,
    float c[2][4][4], float* sAh, float* sBh, int tid) {
    int lane = tid & 31;
    int warpM = (tid >> 5) & 3;
    int warpN = tid >> 7;
    int grp = lane >> 2, qd = lane & 3;

    int am0 = tid >> 2;
    int ak = (tid & 3) * 4;
    const float* pa0 = A + (size_t)(mBase + am0) * NC + ak;
    const float* pa1 = A + (size_t)(mBase + am0 + 64) * NC + ak;
    const float* pb  = W + (size_t)am0 * NC + ak;

    float4 ra0 = *(const float4*)pa0;
    float4 ra1 = *(const float4*)pa1;
    float4 rb  = *(const float4*)pb;

    for (int kt = 0; kt < NC / 16; ++kt) {
        __syncthreads();
        sts_cvt(sAh, am0 * PA + ak, ra0);
        sts_cvt(sAh, (am0 + 64) * PA + ak, ra1);
        sts_cvt(sBh, am0 * PA + ak, rb);
        __syncthreads();
        if (kt < NC / 16 - 1) {
            int k0 = (kt + 1) * 16;
            ra0 = *(const float4*)(pa0 + k0);
            ra1 = *(const float4*)(pa1 + k0);
            rb  = *(const float4*)(pb + k0);
        }
#pragma unroll
        for (int kk = 0; kk < 16; kk += 8) {
            uint32_t ah[2][4], bhf[4][2];
#pragma unroll
            for (int mi = 0; mi < 2; ++mi) {
                int r = warpM * 32 + mi * 16 + grp;
                const float* ph = sAh + r * PA + kk + qd;
                ah[mi][0] = __float_as_uint(ph[0]);
                ah[mi][1] = __float_as_uint(ph[8 * PA]);
                ah[mi][2] = __float_as_uint(ph[4]);
                ah[mi][3] = __float_as_uint(ph[8 * PA + 4]);
            }
#pragma unroll
            for (int nj = 0; nj < 4; ++nj) {
                int cn = warpN * 32 + nj * 8 + grp;
                const float* pkh = sBh + cn * PA + kk + qd;
                bhf[nj][0] = __float_as_uint(pkh[0]);
                bhf[nj][1] = __float_as_uint(pkh[4]);
            }
#pragma unroll
            for (int mi = 0; mi < 2; ++mi)
#pragma unroll
                for (int nj = 0; nj < 4; ++nj)
                    mma_tf32(c[mi][nj], ah[mi], bhf[nj]);
        }
    }
}

// ---------------------------------------------------------------------------
// fp32 helper GEMM pieces (K1 / K4)
// ---------------------------------------------------------------------------
__device__ __forceinline__ void load_A_tile(const float* __restrict__ A,
                                            int mBase, int k0, float* As, int tid) {
#pragma unroll
    for (int l = 0; l < 2; ++l) {
        int lin = tid * 2 + l;
        int m = lin >> 2;
        int kg = (lin & 3) * 4;
        float4 v = *(const float4*)(A + (size_t)(mBase + m) * NC + k0 + kg);
        As[(kg + 0) * AP + m] = v.x;
        As[(kg + 1) * AP + m] = v.y;
        As[(kg + 2) * AP + m] = v.z;
        As[(kg + 3) * AP + m] = v.w;
    }
}

__device__ __forceinline__ void load_B_tile(const float* __restrict__ W,
                                            int nBase, int k0, float* Bs, int tid) {
    int wr = tid >> 2;
    int kg = (tid & 3) * 4;
    float4 v = *(const float4*)(W + (size_t)(nBase + wr) * NC + k0 + kg);
    Bs[(kg + 0) * BP2 + wr] = v.x;
    Bs[(kg + 1) * BP2 + wr] = v.y;
    Bs[(kg + 2) * BP2 + wr] = v.z;
    Bs[(kg + 3) * BP2 + wr] = v.w;
}

__device__ __forceinline__ void mma_tile(const float* As, const float* Bs,
                                         float c[8][4], int trow, int tcol) {
#pragma unroll
    for (int k = 0; k < BK; ++k) {
        float4 a0 = *(const float4*)(As + k * AP + trow * 8);
        float4 a1 = *(const float4*)(As + k * AP + trow * 8 + 4);
        float4 b0 = *(const float4*)(Bs + k * BP2 + tcol * 4);
        float a[8] = {a0.x, a0.y, a0.z, a0.w, a1.x, a1.y, a1.z, a1.w};
        float b[4] = {b0.x, b0.y, b0.z, b0.w};
#pragma unroll
        for (int i = 0; i < 8; ++i)
#pragma unroll
            for (int j = 0; j < 4; ++j)
                c[i][j] += a[i] * b[j];
    }
}

// ---------------------------------------------------------------------------
// K0: zero accumulators + flag state
// ---------------------------------------------------------------------------
__global__ void k_zero() {
    int i = blockIdx.x * blockDim.x + threadIdx.x;
    if (i < NB * NH * NG * ND) g_acc[i] = 0.0f;
    if (i < NB * NH * NG) g_cnt[i] = 0;
    if (i < NB * NH) { g_qmax[i] = 0.0f; g_fcnt[i] = 0; }
}

// ---------------------------------------------------------------------------
// K1: q projection -> g_qT[bh][d][n], plus per-bh max ||q_n||^2
// ---------------------------------------------------------------------------
__global__ void __launch_bounds__(256) k_qproj(const float* __restrict__ query,
                                               const float* __restrict__ Wq) {
    __shared__ float As[BK * AP];
    __shared__ float Bs[BK * BP2];
    int tid = threadIdx.x;
    int trow = tid >> 4, tcol = tid & 15;
    int mBase = blockIdx.x * BM;
    int h = blockIdx.y;

    float c[8][4] = {};
    for (int k0 = 0; k0 < NC; k0 += BK) {
        load_A_tile(query, mBase, k0, As, tid);
        load_B_tile(Wq, h * 64, k0, Bs, tid);
        __syncthreads();
        mma_tile(As, Bs, c, trow, tcol);
        __syncthreads();
    }
#pragma unroll
    for (int i = 0; i < 8; ++i) {
        int m = mBase + trow * 8 + i;
        int b = m >> 6, n = m & 63;
        int bh = b * NH + h;
        float qn2 = 0.0f;
#pragma unroll
        for (int j = 0; j < 4; ++j) {
            int d = tcol * 4 + j;
            g_qT[((size_t)bh * ND + d) * NG + n] = c[i][j];
            qn2 += c[i][j] * c[i][j];
        }
#pragma unroll
        for (int off = 8; off >= 1; off >>= 1)
            qn2 += __shfl_xor_sync(0xffffffffu, qn2, off, 16);
        if (tcol == 0)
            atomicMax((unsigned int*)&g_qmax[bh], __float_as_uint(qn2));
    }
}

// ---------------------------------------------------------------------------
// K2: kp = key@Wk^T via 1xTF32 + fp32 score epilogue with top-2 margin test
// ---------------------------------------------------------------------------
__global__ void __launch_bounds__(256) k2_assign(const float* __restrict__ key,
                                                 const float* __restrict__ Wk) {
    __shared__ __align__(16) union {
        struct { float Ah[128 * PA]; float Bh[64 * PA]; } g;
        struct { float Kp[128 * 64]; float Qs[64 * 64]; } e;   // 48 KB
    } sm;

    int tid = threadIdx.x;
    int lane = tid & 31;
    int warpM = (tid >> 5) & 3, warpN = tid >> 7;
    int grp = lane >> 2, qd = lane & 3;

    int mBase = blockIdx.x * 128;
    int b = mBase >> 12;
    int sBase = mBase & (NS - 1);
    int h = blockIdx.y;
    int bh = b * NH + h;

    float cs[2][4][4] = {};
    gemm_tf32_1x(key, Wk + (size_t)h * 64 * NC, mBase, cs,
                 sm.g.Ah, sm.g.Bh, tid);

    __syncthreads();

#pragma unroll
    for (int mi = 0; mi < 2; ++mi)
#pragma unroll
        for (int nj = 0; nj < 4; ++nj) {
            int row = warpM * 32 + mi * 16 + grp;
            int col = warpN * 32 + nj * 8 + 2 * qd;
            *(float2*)&sm.e.Kp[row * 64 + col] =
                make_float2(cs[mi][nj][0], cs[mi][nj][1]);
            *(float2*)&sm.e.Kp[(row + 8) * 64 + col] =
                make_float2(cs[mi][nj][2], cs[mi][nj][3]);
        }
    {
        const float* qsrc = g_qT + (size_t)bh * ND * NG;
#pragma unroll
        for (int r = 0; r < 4; ++r) {
            int off = (tid + 256 * r) * 4;
            *(float4*)&sm.e.Qs[off] = *(const float4*)&qsrc[off];
        }
    }
    __syncthreads();

    float qmax = sqrtf(g_qmax[bh]);

    int tr = tid >> 4, tc = tid & 15;
    float acc2[8][4] = {};
    float akk[8] = {};
#pragma unroll 8
    for (int d = 0; d < 64; ++d) {
        float4 q4 = *(const float4*)&sm.e.Qs[d * 64 + tc * 4];
#pragma unroll
        for (int i = 0; i < 8; ++i) {
            float a = sm.e.Kp[(tr * 8 + i) * 64 + d];
            acc2[i][0] += a * q4.x;
            acc2[i][1] += a * q4.y;
            acc2[i][2] += a * q4.z;
            acc2[i][3] += a * q4.w;
            akk[i] += a * a;
        }
    }
#pragma unroll
    for (int i = 0; i < 8; ++i) {
        float m1 = acc2[i][0], m2 = -3.4e38f;
        int i1 = tc * 4;
#pragma unroll
        for (int j = 1; j < 4; ++j) {
            float v = acc2[i][j];
            if (v > m1) { m2 = m1; m1 = v; i1 = tc * 4 + j; }
            else if (v > m2) m2 = v;
        }
#pragma unroll
        for (int off = 8; off >= 1; off >>= 1) {
            float om1 = __shfl_down_sync(0xffffffffu, m1, off, 16);
            int   oi1 = __shfl_down_sync(0xffffffffu, i1, off, 16);
            float om2 = __shfl_down_sync(0xffffffffu, m2, off, 16);
            if (om1 > m1) { m2 = fmaxf(m1, om2); m1 = om1; i1 = oi1; }
            else          { m2 = fmaxf(m2, om1); }
        }
        if (tc == 0) {
            int s = sBase + tr * 8 + i;
            g_idx[bh * NS + s] = i1;
            atomicAdd(&g_cnt[bh * NG + i1], 1);
            float T = TC * sqrtf(akk[i]) * qmax;
            if (m1 - m2 < T) {
                int p = atomicAdd(&g_fcnt[bh], 1);
                g_flag[bh * NS + p] = s;
            }
        }
    }
}

// ---------------------------------------------------------------------------
// K2b: batched fp32 recompute of flagged tokens (per-bh mini-GEMM)
// grid = (96, RSPLIT): block (bh, j) handles chunks j, j+RSPLIT, ... of bh
// ---------------------------------------------------------------------------
__global__ void __launch_bounds__(256) k_repair(const float* __restrict__ key,
                                                const float* __restrict__ Wk) {
    __shared__ __align__(16) union {
        struct { float A[64 * RP]; float B[64 * RP]; } g;  // 18432 B
        float Q[64 * 64];                                  // 16384 B
    } u;
    __shared__ __align__(16) float Kp[64 * 68];
    __shared__ int sS[64];

    int tid = threadIdx.x;
    int bh = blockIdx.x;
    int b = bh / NH, h = bh % NH;
    int nf = g_fcnt[bh];
    const float* qsrc = g_qT + (size_t)bh * ND * NG;

    int ttr = tid >> 4, ttc = tid & 15;
    int lr = tid >> 2;              // 0..63
    int cg = (tid & 3) * 8;         // 0,8,16,24
    const float* wrow = Wk + (size_t)(h * 64 + lr) * NC + cg;

    for (int c0 = blockIdx.y * 64; c0 < nf; c0 += RSPLIT * 64) {
        __syncthreads();
        if (tid < 64) {
            int i = c0 + tid;
            sS[tid] = g_flag[bh * NS + (i < nf ? i : nf - 1)];
        }
        __syncthreads();

        float acc[4][4] = {};
        const float* krow = key + ((size_t)b * NS + sS[lr]) * NC + cg;
        for (int kt = 0; kt < NC / 32; ++kt) {
            int kof = kt * 32;
            *(float4*)&u.g.A[lr * RP + cg]     = *(const float4*)(krow + kof);
            *(float4*)&u.g.A[lr * RP + cg + 4] = *(const float4*)(krow + kof + 4);
            *(float4*)&u.g.B[lr * RP + cg]     = *(const float4*)(wrow + kof);
            *(float4*)&u.g.B[lr * RP + cg + 4] = *(const float4*)(wrow + kof + 4);
            __syncthreads();
#pragma unroll 8
            for (int c = 0; c < 32; ++c) {
                float a[4], bb[4];
#pragma unroll
                for (int i = 0; i < 4; ++i) a[i] = u.g.A[(ttr * 4 + i) * RP + c];
#pragma unroll
                for (int j = 0; j < 4; ++j) bb[j] = u.g.B[(ttc * 4 + j) * RP + c];
#pragma unroll
                for (int i = 0; i < 4; ++i)
#pragma unroll
                    for (int j = 0; j < 4; ++j)
                        acc[i][j] += a[i] * bb[j];
            }
            __syncthreads();
        }
        // kp -> smem, then q tile (overwrites A/B)
#pragma unroll
        for (int i = 0; i < 4; ++i)
#pragma unroll
            for (int j = 0; j < 4; ++j)
                Kp[(ttr * 4 + i) * 68 + ttc * 4 + j] = acc[i][j];
#pragma unroll
        for (int r = 0; r < 4; ++r) {
            int off = (tid + 256 * r) * 4;
            *(float4*)&u.Q[off] = *(const float4*)&qsrc[off];
        }
        __syncthreads();

        // fp32 scores + argmax (reference association: dot over d ascending)
        float s2[4][4] = {};
#pragma unroll 8
        for (int d = 0; d < 64; ++d) {
            float4 q4 = *(const float4*)&u.Q[d * 64 + ttc * 4];
#pragma unroll
            for (int i = 0; i < 4; ++i) {
                float a = Kp[(ttr * 4 + i) * 68 + d];
                s2[i][0] += a * q4.x;
                s2[i][1] += a * q4.y;
                s2[i][2] += a * q4.z;
                s2[i][3] += a * q4.w;
            }
        }
#pragma unroll
        for (int i = 0; i < 4; ++i) {
            float mv = s2[i][0];
            int mi = ttc * 4;
#pragma unroll
            for (int j = 1; j < 4; ++j)
                if (s2[i][j] > mv) { mv = s2[i][j]; mi = ttc * 4 + j; }
#pragma unroll
            for (int off = 8; off >= 1; off >>= 1) {
                float ov = __shfl_down_sync(0xffffffffu, mv, off, 16);
                int   oi = __shfl_down_sync(0xffffffffu, mi, off, 16);
                if (ov > mv || (ov == mv && oi < mi)) { mv = ov; mi = oi; }
            }
            int row = ttr * 4 + i;
            if (ttc == 0 && c0 + row < nf) {
                int s = sS[row];
                int old = g_idx[bh * NS + s];
                if (old != mi) {
                    g_idx[bh * NS + s] = mi;
                    atomicAdd(&g_cnt[bh * NG + old], -1);
                    atomicAdd(&g_cnt[bh * NG + mi], 1);
                }
            }
        }
    }
}

// ---------------------------------------------------------------------------
// K3: vp = key@Wv^T via 1xTF32 + fused atomic scatter (R3-identical)
// ---------------------------------------------------------------------------
__global__ void __launch_bounds__(256) k3_scatter(const float* __restrict__ key,
                                                  const float* __restrict__ Wv) {
    __shared__ __align__(16) float Ah[128 * PA];
    __shared__ __align__(16) float Bvh[64 * PA];

    int tid = threadIdx.x;
    int lane = tid & 31;
    int warpM = (tid >> 5) & 3, warpN = tid >> 7;
    int grp = lane >> 2, qd = lane & 3;

    int mBase = blockIdx.x * 128;
    int b = mBase >> 12;
    int sBase = mBase & (NS - 1);
    int h = blockIdx.y;
    int bh = b * NH + h;

    float cv[2][4][4] = {};
    gemm_tf32_1x(key, Wv + (size_t)h * 64 * NC, mBase, cv, Ah, Bvh, tid);

#pragma unroll
    for (int mi = 0; mi < 2; ++mi) {
        int s0 = sBase + warpM * 32 + mi * 16 + grp;
        int n0 = g_idx[bh * NS + s0];
        int n1 = g_idx[bh * NS + s0 + 8];
#pragma unroll
        for (int nj = 0; nj < 4; ++nj) {
            int d = warpN * 32 + nj * 8 + 2 * qd;
            float* p0 = &g_acc[(bh * NG + n0) * ND + d];
            atomicAdd(p0,     cv[mi][nj][0]);
            atomicAdd(p0 + 1, cv[mi][nj][1]);
            float* p1 = &g_acc[(bh * NG + n1) * ND + d];
            atomicAdd(p1,     cv[mi][nj][2]);
            atomicAdd(p1 + 1, cv[mi][nj][3]);
        }
    }
}

// ---------------------------------------------------------------------------
// K4: normalize + out = tmp @ Wp^T + bp
// ---------------------------------------------------------------------------
__global__ void __launch_bounds__(256) k_finalize(const float* __restrict__ Wp,
                                                  const float* __restrict__ bp,
                                                  float* __restrict__ out) {
    __shared__ float As[BK * AP];
    __shared__ float Bs[BK * BP2];
    int tid = threadIdx.x;
    int trow = tid >> 4, tcol = tid & 15;
    int mBase = blockIdx.x * BM;
    int nBase = blockIdx.y * BN;

    float c[8][4] = {};
    for (int k0 = 0; k0 < NC; k0 += BK) {
#pragma unroll
        for (int l = 0; l < 2; ++l) {
            int lin = tid * 2 + l;
            int m = lin >> 2;
            int kg = (lin & 3) * 4;
            int gm = mBase + m;
            int b = gm >> 6, n = gm & 63;
            int cc = k0 + kg;
            int h = cc >> 6, d = cc & 63;
            int bh = b * NH + h;
            float inv = 1.0f / (float)(g_cnt[bh * NG + n] + 1);
            float4 v = *(const float4*)&g_acc[(bh * NG + n) * ND + d];
            As[(kg + 0) * AP + m] = v.x * inv;
            As[(kg + 1) * AP + m] = v.y * inv;
            As[(kg + 2) * AP + m] = v.z * inv;
            As[(kg + 3) * AP + m] = v.w * inv;
        }
        load_B_tile(Wp, nBase, k0, Bs, tid);
        __syncthreads();
        mma_tile(As, Bs, c, trow, tcol);
        __syncthreads();
    }

    float4 bias = *(const float4*)&bp[nBase + tcol * 4];
#pragma unroll
    for (int i = 0; i < 8; ++i) {
        int m = mBase + trow * 8 + i;
        float4 v = make_float4(c[i][0] + bias.x, c[i][1] + bias.y,
                               c[i][2] + bias.z, c[i][3] + bias.w);
        *(float4*)&out[(size_t)m * NC + nBase + tcol * 4] = v;
    }
}

// ---------------------------------------------------------------------------
extern "C" void kernel_launch(void* const* d_in, const int* in_sizes, int n_in,
                              void* d_out, int out_size) {
    const float* query = (const float*)d_in[0];
    const float* key   = (const float*)d_in[1];
    const float* Wq    = (const float*)d_in[2];
    const float* Wk    = (const float*)d_in[3];
    const float* Wv    = (const float*)d_in[4];
    const float* Wp    = (const float*)d_in[5];
    const float* bp    = (const float*)d_in[6];
    float* out = (float*)d_out;

    k_zero<<<(NB * NH * NG * ND + 255) / 256, 256>>>();
    k_qproj<<<dim3(8, 6), 256>>>(query, Wq);
    k2_assign<<<dim3((NB * NS) / 128, NH), 256>>>(key, Wk);
    k_repair<<<dim3(NB * NH, RSPLIT), 256>>>(key, Wk);
    k3_scatter<<<dim3((NB * NS) / 128, NH), 256>>>(key, Wv);
    k_finalize<<<dim3(8, 6), 256>>>(Wp, bp, out);
}

// round 15
// speedup vs baseline: 2.1417x; 1.0030x over previous
#include <cuda_runtime.h>
#include <cstdint>

// Problem constants
#define NB 16
#define NG 64
#define NS 4096
#define NC 384
#define NH 6
#define ND 64

// fp32 helper-GEMM tile config (K1/K4, small)
#define BM 128
#define BN 64
#define BK 16
#define AP 132
#define BP2 68

// tf32 GEMM smem pitch
#define PA 20

// repair GEMM smem pitch (floats; 36*4=144 B keeps float4 rows 16B-aligned)
#define RP 36
// repair parallelism: chunk-slices per bucket (1 chunk per block up to 32)
#define RSPLIT 32

// flag threshold coefficient (gap < TC * ||kp|| * max||q|| -> recompute)
#define TC 2.0e-3f

// Scratch
__device__ __align__(16) float g_qT[NB * NH * ND * NG];   // q^T: [bh][d][n]
__device__ int   g_idx[NB * NH * NS];
__device__ __align__(16) float g_acc[NB * NH * NG * ND];
__device__ int   g_cnt[NB * NH * NG];
__device__ float g_qmax[NB * NH];
__device__ int   g_fcnt[NB * NH];
__device__ int   g_flag[NB * NH * NS];     // per-bh buckets of flagged s

// ---------------------------------------------------------------------------
// tf32 helpers
// ---------------------------------------------------------------------------
__device__ __forceinline__ uint32_t f2tf(float x) {
    uint32_t u;
    asm("cvt.rna.tf32.f32 %0, %1;" : "=r"(u) : "f"(x));
    return u;
}

__device__ __forceinline__ void mma_tf32(float c[4], const uint32_t a[4],
                                         const uint32_t b[2]) {
    asm volatile(
        "mma.sync.aligned.m16n8k8.row.col.f32.tf32.tf32.f32 "
        "{%0,%1,%2,%3}, {%4,%5,%6,%7}, {%8,%9}, {%0,%1,%2,%3};"
        : "+f"(c[0]), "+f"(c[1]), "+f"(c[2]), "+f"(c[3])
        : "r"(a[0]), "r"(a[1]), "r"(a[2]), "r"(a[3]), "r"(b[0]), "r"(b[1]));
}

__device__ __forceinline__ void sts_cvt(float* hi, int off, float4 v) {
    hi[off + 0] = __uint_as_float(f2tf(v.x));
    hi[off + 1] = __uint_as_float(f2tf(v.y));
    hi[off + 2] = __uint_as_float(f2tf(v.z));
    hi[off + 3] = __uint_as_float(f2tf(v.w));
}

// ---------------------------------------------------------------------------
// 128x64 block tile 1xTF32 GEMM core (R3/R11-proven)
// ---------------------------------------------------------------------------
__device__ __forceinline__ void gemm_tf32_1x(
    const float* __restrict__ A, const float* __restrict__ W, int mBase,
    float c[2][4][4], float* sAh, float* sBh, int tid) {
    int lane = tid & 31;
    int warpM = (tid >> 5) & 3;
    int warpN = tid >> 7;
    int grp = lane >> 2, qd = lane & 3;

    int am0 = tid >> 2;
    int ak = (tid & 3) * 4;
    const float* pa0 = A + (size_t)(mBase + am0) * NC + ak;
    const float* pa1 = A + (size_t)(mBase + am0 + 64) * NC + ak;
    const float* pb  = W + (size_t)am0 * NC + ak;

    float4 ra0 = *(const float4*)pa0;
    float4 ra1 = *(const float4*)pa1;
    float4 rb  = *(const float4*)pb;

    for (int kt = 0; kt < NC / 16; ++kt) {
        __syncthreads();
        sts_cvt(sAh, am0 * PA + ak, ra0);
        sts_cvt(sAh, (am0 + 64) * PA + ak, ra1);
        sts_cvt(sBh, am0 * PA + ak, rb);
        __syncthreads();
        if (kt < NC / 16 - 1) {
            int k0 = (kt + 1) * 16;
            ra0 = *(const float4*)(pa0 + k0);
            ra1 = *(const float4*)(pa1 + k0);
            rb  = *(const float4*)(pb + k0);
        }
#pragma unroll
        for (int kk = 0; kk < 16; kk += 8) {
            uint32_t ah[2][4], bhf[4][2];
#pragma unroll
            for (int mi = 0; mi < 2; ++mi) {
                int r = warpM * 32 + mi * 16 + grp;
                const float* ph = sAh + r * PA + kk + qd;
                ah[mi][0] = __float_as_uint(ph[0]);
                ah[mi][1] = __float_as_uint(ph[8 * PA]);
                ah[mi][2] = __float_as_uint(ph[4]);
                ah[mi][3] = __float_as_uint(ph[8 * PA + 4]);
            }
#pragma unroll
            for (int nj = 0; nj < 4; ++nj) {
                int cn = warpN * 32 + nj * 8 + grp;
                const float* pkh = sBh + cn * PA + kk + qd;
                bhf[nj][0] = __float_as_uint(pkh[0]);
                bhf[nj][1] = __float_as_uint(pkh[4]);
            }
#pragma unroll
            for (int mi = 0; mi < 2; ++mi)
#pragma unroll
                for (int nj = 0; nj < 4; ++nj)
                    mma_tf32(c[mi][nj], ah[mi], bhf[nj]);
        }
    }
}

// ---------------------------------------------------------------------------
// fp32 helper GEMM pieces (K1 / K4)
// ---------------------------------------------------------------------------
__device__ __forceinline__ void load_A_tile(const float* __restrict__ A,
                                            int mBase, int k0, float* As, int tid) {
#pragma unroll
    for (int l = 0; l < 2; ++l) {
        int lin = tid * 2 + l;
        int m = lin >> 2;
        int kg = (lin & 3) * 4;
        float4 v = *(const float4*)(A + (size_t)(mBase + m) * NC + k0 + kg);
        As[(kg + 0) * AP + m] = v.x;
        As[(kg + 1) * AP + m] = v.y;
        As[(kg + 2) * AP + m] = v.z;
        As[(kg + 3) * AP + m] = v.w;
    }
}

__device__ __forceinline__ void load_B_tile(const float* __restrict__ W,
                                            int nBase, int k0, float* Bs, int tid) {
    int wr = tid >> 2;
    int kg = (tid & 3) * 4;
    float4 v = *(const float4*)(W + (size_t)(nBase + wr) * NC + k0 + kg);
    Bs[(kg + 0) * BP2 + wr] = v.x;
    Bs[(kg + 1) * BP2 + wr] = v.y;
    Bs[(kg + 2) * BP2 + wr] = v.z;
    Bs[(kg + 3) * BP2 + wr] = v.w;
}

__device__ __forceinline__ void mma_tile(const float* As, const float* Bs,
                                         float c[8][4], int trow, int tcol) {
#pragma unroll
    for (int k = 0; k < BK; ++k) {
        float4 a0 = *(const float4*)(As + k * AP + trow * 8);
        float4 a1 = *(const float4*)(As + k * AP + trow * 8 + 4);
        float4 b0 = *(const float4*)(Bs + k * BP2 + tcol * 4);
        float a[8] = {a0.x, a0.y, a0.z, a0.w, a1.x, a1.y, a1.z, a1.w};
        float b[4] = {b0.x, b0.y, b0.z, b0.w};
#pragma unroll
        for (int i = 0; i < 8; ++i)
#pragma unroll
            for (int j = 0; j < 4; ++j)
                c[i][j] += a[i] * b[j];
    }
}

// ---------------------------------------------------------------------------
// K0: zero accumulators + flag state
// ---------------------------------------------------------------------------
__global__ void k_zero() {
    int i = blockIdx.x * blockDim.x + threadIdx.x;
    if (i < NB * NH * NG * ND) g_acc[i] = 0.0f;
    if (i < NB * NH * NG) g_cnt[i] = 0;
    if (i < NB * NH) { g_qmax[i] = 0.0f; g_fcnt[i] = 0; }
}

// ---------------------------------------------------------------------------
// K1: q projection -> g_qT[bh][d][n], plus per-bh max ||q_n||^2
// ---------------------------------------------------------------------------
__global__ void __launch_bounds__(256) k_qproj(const float* __restrict__ query,
                                               const float* __restrict__ Wq) {
    __shared__ float As[BK * AP];
    __shared__ float Bs[BK * BP2];
    int tid = threadIdx.x;
    int trow = tid >> 4, tcol = tid & 15;
    int mBase = blockIdx.x * BM;
    int h = blockIdx.y;

    float c[8][4] = {};
    for (int k0 = 0; k0 < NC; k0 += BK) {
        load_A_tile(query, mBase, k0, As, tid);
        load_B_tile(Wq, h * 64, k0, Bs, tid);
        __syncthreads();
        mma_tile(As, Bs, c, trow, tcol);
        __syncthreads();
    }
#pragma unroll
    for (int i = 0; i < 8; ++i) {
        int m = mBase + trow * 8 + i;
        int b = m >> 6, n = m & 63;
        int bh = b * NH + h;
        float qn2 = 0.0f;
#pragma unroll
        for (int j = 0; j < 4; ++j) {
            int d = tcol * 4 + j;
            g_qT[((size_t)bh * ND + d) * NG + n] = c[i][j];
            qn2 += c[i][j] * c[i][j];
        }
#pragma unroll
        for (int off = 8; off >= 1; off >>= 1)
            qn2 += __shfl_xor_sync(0xffffffffu, qn2, off, 16);
        if (tcol == 0)
            atomicMax((unsigned int*)&g_qmax[bh], __float_as_uint(qn2));
    }
}

// ---------------------------------------------------------------------------
// K2: kp = key@Wk^T via 1xTF32 + fp32 score epilogue with top-2 margin test
// ---------------------------------------------------------------------------
__global__ void __launch_bounds__(256) k2_assign(const float* __restrict__ key,
                                                 const float* __restrict__ Wk) {
    __shared__ __align__(16) union {
        struct { float Ah[128 * PA]; float Bh[64 * PA]; } g;
        struct { float Kp[128 * 64]; float Qs[64 * 64]; } e;   // 48 KB
    } sm;

    int tid = threadIdx.x;
    int lane = tid & 31;
    int warpM = (tid >> 5) & 3, warpN = tid >> 7;
    int grp = lane >> 2, qd = lane & 3;

    int mBase = blockIdx.x * 128;
    int b = mBase >> 12;
    int sBase = mBase & (NS - 1);
    int h = blockIdx.y;
    int bh = b * NH + h;

    float cs[2][4][4] = {};
    gemm_tf32_1x(key, Wk + (size_t)h * 64 * NC, mBase, cs,
                 sm.g.Ah, sm.g.Bh, tid);

    __syncthreads();

#pragma unroll
    for (int mi = 0; mi < 2; ++mi)
#pragma unroll
        for (int nj = 0; nj < 4; ++nj) {
            int row = warpM * 32 + mi * 16 + grp;
            int col = warpN * 32 + nj * 8 + 2 * qd;
            *(float2*)&sm.e.Kp[row * 64 + col] =
                make_float2(cs[mi][nj][0], cs[mi][nj][1]);
            *(float2*)&sm.e.Kp[(row + 8) * 64 + col] =
                make_float2(cs[mi][nj][2], cs[mi][nj][3]);
        }
    {
        const float* qsrc = g_qT + (size_t)bh * ND * NG;
#pragma unroll
        for (int r = 0; r < 4; ++r) {
            int off = (tid + 256 * r) * 4;
            *(float4*)&sm.e.Qs[off] = *(const float4*)&qsrc[off];
        }
    }
    __syncthreads();

    float qmax = sqrtf(g_qmax[bh]);

    int tr = tid >> 4, tc = tid & 15;
    float acc2[8][4] = {};
    float akk[8] = {};
#pragma unroll 8
    for (int d = 0; d < 64; ++d) {
        float4 q4 = *(const float4*)&sm.e.Qs[d * 64 + tc * 4];
#pragma unroll
        for (int i = 0; i < 8; ++i) {
            float a = sm.e.Kp[(tr * 8 + i) * 64 + d];
            acc2[i][0] += a * q4.x;
            acc2[i][1] += a * q4.y;
            acc2[i][2] += a * q4.z;
            acc2[i][3] += a * q4.w;
            akk[i] += a * a;
        }
    }
#pragma unroll
    for (int i = 0; i < 8; ++i) {
        float m1 = acc2[i][0], m2 = -3.4e38f;
        int i1 = tc * 4;
#pragma unroll
        for (int j = 1; j < 4; ++j) {
            float v = acc2[i][j];
            if (v > m1) { m2 = m1; m1 = v; i1 = tc * 4 + j; }
            else if (v > m2) m2 = v;
        }
#pragma unroll
        for (int off = 8; off >= 1; off >>= 1) {
            float om1 = __shfl_down_sync(0xffffffffu, m1, off, 16);
            int   oi1 = __shfl_down_sync(0xffffffffu, i1, off, 16);
            float om2 = __shfl_down_sync(0xffffffffu, m2, off, 16);
            if (om1 > m1) { m2 = fmaxf(m1, om2); m1 = om1; i1 = oi1; }
            else          { m2 = fmaxf(m2, om1); }
        }
        if (tc == 0) {
            int s = sBase + tr * 8 + i;
            g_idx[bh * NS + s] = i1;
            atomicAdd(&g_cnt[bh * NG + i1], 1);
            float T = TC * sqrtf(akk[i]) * qmax;
            if (m1 - m2 < T) {
                int p = atomicAdd(&g_fcnt[bh], 1);
                g_flag[bh * NS + p] = s;
            }
        }
    }
}

// ---------------------------------------------------------------------------
// K2b: batched fp32 recompute of flagged tokens (per-bh mini-GEMM)
// grid = (96, RSPLIT): block (bh, j) handles chunks j, j+RSPLIT, ... of bh
// ---------------------------------------------------------------------------
__global__ void __launch_bounds__(256) k_repair(const float* __restrict__ key,
                                                const float* __restrict__ Wk) {
    __shared__ __align__(16) union {
        struct { float A[64 * RP]; float B[64 * RP]; } g;  // 18432 B
        float Q[64 * 64];                                  // 16384 B
    } u;
    __shared__ __align__(16) float Kp[64 * 68];
    __shared__ int sS[64];

    int tid = threadIdx.x;
    int bh = blockIdx.x;
    int b = bh / NH, h = bh % NH;
    int nf = g_fcnt[bh];
    const float* qsrc = g_qT + (size_t)bh * ND * NG;

    int ttr = tid >> 4, ttc = tid & 15;
    int lr = tid >> 2;              // 0..63
    int cg = (tid & 3) * 8;         // 0,8,16,24
    const float* wrow = Wk + (size_t)(h * 64 + lr) * NC + cg;

    for (int c0 = blockIdx.y * 64; c0 < nf; c0 += RSPLIT * 64) {
        __syncthreads();
        if (tid < 64) {
            int i = c0 + tid;
            sS[tid] = g_flag[bh * NS + (i < nf ? i : nf - 1)];
        }
        __syncthreads();

        float acc[4][4] = {};
        const float* krow = key + ((size_t)b * NS + sS[lr]) * NC + cg;
        for (int kt = 0; kt < NC / 32; ++kt) {
            int kof = kt * 32;
            *(float4*)&u.g.A[lr * RP + cg]     = *(const float4*)(krow + kof);
            *(float4*)&u.g.A[lr * RP + cg + 4] = *(const float4*)(krow + kof + 4);
            *(float4*)&u.g.B[lr * RP + cg]     = *(const float4*)(wrow + kof);
            *(float4*)&u.g.B[lr * RP + cg + 4] = *(const float4*)(wrow + kof + 4);
            __syncthreads();
#pragma unroll 8
            for (int c = 0; c < 32; ++c) {
                float a[4], bb[4];
#pragma unroll
                for (int i = 0; i < 4; ++i) a[i] = u.g.A[(ttr * 4 + i) * RP + c];
#pragma unroll
                for (int j = 0; j < 4; ++j) bb[j] = u.g.B[(ttc * 4 + j) * RP + c];
#pragma unroll
                for (int i = 0; i < 4; ++i)
#pragma unroll
                    for (int j = 0; j < 4; ++j)
                        acc[i][j] += a[i] * bb[j];
            }
            __syncthreads();
        }
        // kp -> smem, then q tile (overwrites A/B)
#pragma unroll
        for (int i = 0; i < 4; ++i)
#pragma unroll
            for (int j = 0; j < 4; ++j)
                Kp[(ttr * 4 + i) * 68 + ttc * 4 + j] = acc[i][j];
#pragma unroll
        for (int r = 0; r < 4; ++r) {
            int off = (tid + 256 * r) * 4;
            *(float4*)&u.Q[off] = *(const float4*)&qsrc[off];
        }
        __syncthreads();

        // fp32 scores + argmax (reference association: dot over d ascending)
        float s2[4][4] = {};
#pragma unroll 8
        for (int d = 0; d < 64; ++d) {
            float4 q4 = *(const float4*)&u.Q[d * 64 + ttc * 4];
#pragma unroll
            for (int i = 0; i < 4; ++i) {
                float a = Kp[(ttr * 4 + i) * 68 + d];
                s2[i][0] += a * q4.x;
                s2[i][1] += a * q4.y;
                s2[i][2] += a * q4.z;
                s2[i][3] += a * q4.w;
            }
        }
#pragma unroll
        for (int i = 0; i < 4; ++i) {
            float mv = s2[i][0];
            int mi = ttc * 4;
#pragma unroll
            for (int j = 1; j < 4; ++j)
                if (s2[i][j] > mv) { mv = s2[i][j]; mi = ttc * 4 + j; }
#pragma unroll
            for (int off = 8; off >= 1; off >>= 1) {
                float ov = __shfl_down_sync(0xffffffffu, mv, off, 16);
                int   oi = __shfl_down_sync(0xffffffffu, mi, off, 16);
                if (ov > mv || (ov == mv && oi < mi)) { mv = ov; mi = oi; }
            }
            int row = ttr * 4 + i;
            if (ttc == 0 && c0 + row < nf) {
                int s = sS[row];
                int old = g_idx[bh * NS + s];
                if (old != mi) {
                    g_idx[bh * NS + s] = mi;
                    atomicAdd(&g_cnt[bh * NG + old], -1);
                    atomicAdd(&g_cnt[bh * NG + mi], 1);
                }
            }
        }
    }
}

// ---------------------------------------------------------------------------
// K3: vp = key@Wv^T via 1xTF32 + fused atomic scatter (R3-identical)
// ---------------------------------------------------------------------------
__global__ void __launch_bounds__(256) k3_scatter(const float* __restrict__ key,
                                                  const float* __restrict__ Wv) {
    __shared__ __align__(16) float Ah[128 * PA];
    __shared__ __align__(16) float Bvh[64 * PA];

    int tid = threadIdx.x;
    int lane = tid & 31;
    int warpM = (tid >> 5) & 3, warpN = tid >> 7;
    int grp = lane >> 2, qd = lane & 3;

    int mBase = blockIdx.x * 128;
    int b = mBase >> 12;
    int sBase = mBase & (NS - 1);
    int h = blockIdx.y;
    int bh = b * NH + h;

    float cv[2][4][4] = {};
    gemm_tf32_1x(key, Wv + (size_t)h * 64 * NC, mBase, cv, Ah, Bvh, tid);

#pragma unroll
    for (int mi = 0; mi < 2; ++mi) {
        int s0 = sBase + warpM * 32 + mi * 16 + grp;
        int n0 = g_idx[bh * NS + s0];
        int n1 = g_idx[bh * NS + s0 + 8];
#pragma unroll
        for (int nj = 0; nj < 4; ++nj) {
            int d = warpN * 32 + nj * 8 + 2 * qd;
            float* p0 = &g_acc[(bh * NG + n0) * ND + d];
            atomicAdd(p0,     cv[mi][nj][0]);
            atomicAdd(p0 + 1, cv[mi][nj][1]);
            float* p1 = &g_acc[(bh * NG + n1) * ND + d];
            atomicAdd(p1,     cv[mi][nj][2]);
            atomicAdd(p1 + 1, cv[mi][nj][3]);
        }
    }
}

// ---------------------------------------------------------------------------
// K4: normalize + out = tmp @ Wp^T + bp
// ---------------------------------------------------------------------------
__global__ void __launch_bounds__(256) k_finalize(const float* __restrict__ Wp,
                                                  const float* __restrict__ bp,
                                                  float* __restrict__ out) {
    __shared__ float As[BK * AP];
    __shared__ float Bs[BK * BP2];
    int tid = threadIdx.x;
    int trow = tid >> 4, tcol = tid & 15;
    int mBase = blockIdx.x * BM;
    int nBase = blockIdx.y * BN;

    float c[8][4] = {};
    for (int k0 = 0; k0 < NC; k0 += BK) {
#pragma unroll
        for (int l = 0; l < 2; ++l) {
            int lin = tid * 2 + l;
            int m = lin >> 2;
            int kg = (lin & 3) * 4;
            int gm = mBase + m;
            int b = gm >> 6, n = gm & 63;
            int cc = k0 + kg;
            int h = cc >> 6, d = cc & 63;
            int bh = b * NH + h;
            float inv = 1.0f / (float)(g_cnt[bh * NG + n] + 1);
            float4 v = *(const float4*)&g_acc[(bh * NG + n) * ND + d];
            As[(kg + 0) * AP + m] = v.x * inv;
            As[(kg + 1) * AP + m] = v.y * inv;
            As[(kg + 2) * AP + m] = v.z * inv;
            As[(kg + 3) * AP + m] = v.w * inv;
        }
        load_B_tile(Wp, nBase, k0, Bs, tid);
        __syncthreads();
        mma_tile(As, Bs, c, trow, tcol);
        __syncthreads();
    }

    float4 bias = *(const float4*)&bp[nBase + tcol * 4];
#pragma unroll
    for (int i = 0; i < 8; ++i) {
        int m = mBase + trow * 8 + i;
        float4 v = make_float4(c[i][0] + bias.x, c[i][1] + bias.y,
                               c[i][2] + bias.z, c[i][3] + bias.w);
        *(float4*)&out[(size_t)m * NC + nBase + tcol * 4] = v;
    }
}

// ---------------------------------------------------------------------------
extern "C" void kernel_launch(void* const* d_in, const int* in_sizes, int n_in,
                              void* d_out, int out_size) {
    const float* query = (const float*)d_in[0];
    const float* key   = (const float*)d_in[1];
    const float* Wq    = (const float*)d_in[2];
    const float* Wk    = (const float*)d_in[3];
    const float* Wv    = (const float*)d_in[4];
    const float* Wp    = (const float*)d_in[5];
    const float* bp    = (const float*)d_in[6];
    float* out = (float*)d_out;

    k_zero<<<(NB * NH * NG * ND + 255) / 256, 256>>>();
    k_qproj<<<dim3(8, 6), 256>>>(query, Wq);
    k2_assign<<<dim3((NB * NS) / 128, NH), 256>>>(key, Wk);
    k_repair<<<dim3(NB * NH, RSPLIT), 256>>>(key, Wk);
    k3_scatter<<<dim3((NB * NS) / 128, NH), 256>>>(key, Wv);
    k_finalize<<<dim3(8, 6), 256>>>(Wp, bp, out);
}

// round 16
// speedup vs baseline: 2.3398x; 1.0925x over previous
#include <cuda_runtime.h>
#include <cstdint>

// Problem constants
#define NB 16
#define NG 64
#define NS 4096
#define NC 384
#define NH 6
#define ND 64

// fp32 helper-GEMM tile config (K1/K4, small)
#define BM 128
#define BN 64
#define BK 16
#define AP 132
#define BP2 68

// tf32 GEMM smem pitch
#define PA 20

// repair GEMM: A pitch (floats; 36*4=144 B, float4-aligned), Bt pitch
#define RP 36
#define BTP 68
// repair parallelism: chunk-slices per bucket
#define RSPLIT 32

// flag threshold coefficient (gap < TC * ||kp|| * max||q|| -> recompute)
// error model: score-diff err rms ~ 4.5e-3; T = TC*83 = 0.05 -> 11x margin
#define TC 6.0e-4f

// Scratch
__device__ __align__(16) float g_qT[NB * NH * ND * NG];   // q^T: [bh][d][n]
__device__ int   g_idx[NB * NH * NS];
__device__ __align__(16) float g_acc[NB * NH * NG * ND];
__device__ int   g_cnt[NB * NH * NG];
__device__ float g_qmax[NB * NH];
__device__ int   g_fcnt[NB * NH];
__device__ int   g_flag[NB * NH * NS];     // per-bh buckets of flagged s

// ---------------------------------------------------------------------------
// tf32 helpers
// ---------------------------------------------------------------------------
__device__ __forceinline__ uint32_t f2tf(float x) {
    uint32_t u;
    asm("cvt.rna.tf32.f32 %0, %1;" : "=r"(u) : "f"(x));
    return u;
}

__device__ __forceinline__ void mma_tf32(float c[4], const uint32_t a[4],
                                         const uint32_t b[2]) {
    asm volatile(
        "mma.sync.aligned.m16n8k8.row.col.f32.tf32.tf32.f32 "
        "{%0,%1,%2,%3}, {%4,%5,%6,%7}, {%8,%9}, {%0,%1,%2,%3};"
        : "+f"(c[0]), "+f"(c[1]), "+f"(c[2]), "+f"(c[3])
        : "r"(a[0]), "r"(a[1]), "r"(a[2]), "r"(a[3]), "r"(b[0]), "r"(b[1]));
}

__device__ __forceinline__ void sts_cvt(float* hi, int off, float4 v) {
    hi[off + 0] = __uint_as_float(f2tf(v.x));
    hi[off + 1] = __uint_as_float(f2tf(v.y));
    hi[off + 2] = __uint_as_float(f2tf(v.z));
    hi[off + 3] = __uint_as_float(f2tf(v.w));
}

// ---------------------------------------------------------------------------
// 128x64 block tile 1xTF32 GEMM core (R3/R11-proven)
// ---------------------------------------------------------------------------
__device__ __forceinline__ void gemm_tf32_1x(
    const float* __restrict__ A, const float* __restrict__ W, int mBase,
    float c[2][4][4], float* sAh, float* sBh, int tid) {
    int lane = tid & 31;
    int warpM = (tid >> 5) & 3;
    int warpN = tid >> 7;
    int grp = lane >> 2, qd = lane & 3;

    int am0 = tid >> 2;
    int ak = (tid & 3) * 4;
    const float* pa0 = A + (size_t)(mBase + am0) * NC + ak;
    const float* pa1 = A + (size_t)(mBase + am0 + 64) * NC + ak;
    const float* pb  = W + (size_t)am0 * NC + ak;

    float4 ra0 = *(const float4*)pa0;
    float4 ra1 = *(const float4*)pa1;
    float4 rb  = *(const float4*)pb;

    for (int kt = 0; kt < NC / 16; ++kt) {
        __syncthreads();
        sts_cvt(sAh, am0 * PA + ak, ra0);
        sts_cvt(sAh, (am0 + 64) * PA + ak, ra1);
        sts_cvt(sBh, am0 * PA + ak, rb);
        __syncthreads();
        if (kt < NC / 16 - 1) {
            int k0 = (kt + 1) * 16;
            ra0 = *(const float4*)(pa0 + k0);
            ra1 = *(const float4*)(pa1 + k0);
            rb  = *(const float4*)(pb + k0);
        }
#pragma unroll
        for (int kk = 0; kk < 16; kk += 8) {
            uint32_t ah[2][4], bhf[4][2];
#pragma unroll
            for (int mi = 0; mi < 2; ++mi) {
                int r = warpM * 32 + mi * 16 + grp;
                const float* ph = sAh + r * PA + kk + qd;
                ah[mi][0] = __float_as_uint(ph[0]);
                ah[mi][1] = __float_as_uint(ph[8 * PA]);
                ah[mi][2] = __float_as_uint(ph[4]);
                ah[mi][3] = __float_as_uint(ph[8 * PA + 4]);
            }
#pragma unroll
            for (int nj = 0; nj < 4; ++nj) {
                int cn = warpN * 32 + nj * 8 + grp;
                const float* pkh = sBh + cn * PA + kk + qd;
                bhf[nj][0] = __float_as_uint(pkh[0]);
                bhf[nj][1] = __float_as_uint(pkh[4]);
            }
#pragma unroll
            for (int mi = 0; mi < 2; ++mi)
#pragma unroll
                for (int nj = 0; nj < 4; ++nj)
                    mma_tf32(c[mi][nj], ah[mi], bhf[nj]);
        }
    }
}

// ---------------------------------------------------------------------------
// fp32 helper GEMM pieces (K1 / K4)
// ---------------------------------------------------------------------------
__device__ __forceinline__ void load_A_tile(const float* __restrict__ A,
                                            int mBase, int k0, float* As, int tid) {
#pragma unroll
    for (int l = 0; l < 2; ++l) {
        int lin = tid * 2 + l;
        int m = lin >> 2;
        int kg = (lin & 3) * 4;
        float4 v = *(const float4*)(A + (size_t)(mBase + m) * NC + k0 + kg);
        As[(kg + 0) * AP + m] = v.x;
        As[(kg + 1) * AP + m] = v.y;
        As[(kg + 2) * AP + m] = v.z;
        As[(kg + 3) * AP + m] = v.w;
    }
}

__device__ __forceinline__ void load_B_tile(const float* __restrict__ W,
                                            int nBase, int k0, float* Bs, int tid) {
    int wr = tid >> 2;
    int kg = (tid & 3) * 4;
    float4 v = *(const float4*)(W + (size_t)(nBase + wr) * NC + k0 + kg);
    Bs[(kg + 0) * BP2 + wr] = v.x;
    Bs[(kg + 1) * BP2 + wr] = v.y;
    Bs[(kg + 2) * BP2 + wr] = v.z;
    Bs[(kg + 3) * BP2 + wr] = v.w;
}

__device__ __forceinline__ void mma_tile(const float* As, const float* Bs,
                                         float c[8][4], int trow, int tcol) {
#pragma unroll
    for (int k = 0; k < BK; ++k) {
        float4 a0 = *(const float4*)(As + k * AP + trow * 8);
        float4 a1 = *(const float4*)(As + k * AP + trow * 8 + 4);
        float4 b0 = *(const float4*)(Bs + k * BP2 + tcol * 4);
        float a[8] = {a0.x, a0.y, a0.z, a0.w, a1.x, a1.y, a1.z, a1.w};
        float b[4] = {b0.x, b0.y, b0.z, b0.w};
#pragma unroll
        for (int i = 0; i < 8; ++i)
#pragma unroll
            for (int j = 0; j < 4; ++j)
                c[i][j] += a[i] * b[j];
    }
}

// ---------------------------------------------------------------------------
// K0: zero accumulators + flag state
// ---------------------------------------------------------------------------
__global__ void k_zero() {
    int i = blockIdx.x * blockDim.x + threadIdx.x;
    if (i < NB * NH * NG * ND) g_acc[i] = 0.0f;
    if (i < NB * NH * NG) g_cnt[i] = 0;
    if (i < NB * NH) { g_qmax[i] = 0.0f; g_fcnt[i] = 0; }
}

// ---------------------------------------------------------------------------
// K1: q projection -> g_qT[bh][d][n], plus per-bh max ||q_n||^2
// ---------------------------------------------------------------------------
__global__ void __launch_bounds__(256) k_qproj(const float* __restrict__ query,
                                               const float* __restrict__ Wq) {
    __shared__ float As[BK * AP];
    __shared__ float Bs[BK * BP2];
    int tid = threadIdx.x;
    int trow = tid >> 4, tcol = tid & 15;
    int mBase = blockIdx.x * BM;
    int h = blockIdx.y;

    float c[8][4] = {};
    for (int k0 = 0; k0 < NC; k0 += BK) {
        load_A_tile(query, mBase, k0, As, tid);
        load_B_tile(Wq, h * 64, k0, Bs, tid);
        __syncthreads();
        mma_tile(As, Bs, c, trow, tcol);
        __syncthreads();
    }
#pragma unroll
    for (int i = 0; i < 8; ++i) {
        int m = mBase + trow * 8 + i;
        int b = m >> 6, n = m & 63;
        int bh = b * NH + h;
        float qn2 = 0.0f;
#pragma unroll
        for (int j = 0; j < 4; ++j) {
            int d = tcol * 4 + j;
            g_qT[((size_t)bh * ND + d) * NG + n] = c[i][j];
            qn2 += c[i][j] * c[i][j];
        }
#pragma unroll
        for (int off = 8; off >= 1; off >>= 1)
            qn2 += __shfl_xor_sync(0xffffffffu, qn2, off, 16);
        if (tcol == 0)
            atomicMax((unsigned int*)&g_qmax[bh], __float_as_uint(qn2));
    }
}

// ---------------------------------------------------------------------------
// K2: kp = key@Wk^T via 1xTF32 + fp32 score epilogue with top-2 margin test
// ---------------------------------------------------------------------------
__global__ void __launch_bounds__(256) k2_assign(const float* __restrict__ key,
                                                 const float* __restrict__ Wk) {
    __shared__ __align__(16) union {
        struct { float Ah[128 * PA]; float Bh[64 * PA]; } g;
        struct { float Kp[128 * 64]; float Qs[64 * 64]; } e;   // 48 KB
    } sm;

    int tid = threadIdx.x;
    int lane = tid & 31;
    int warpM = (tid >> 5) & 3, warpN = tid >> 7;
    int grp = lane >> 2, qd = lane & 3;

    int mBase = blockIdx.x * 128;
    int b = mBase >> 12;
    int sBase = mBase & (NS - 1);
    int h = blockIdx.y;
    int bh = b * NH + h;

    float cs[2][4][4] = {};
    gemm_tf32_1x(key, Wk + (size_t)h * 64 * NC, mBase, cs,
                 sm.g.Ah, sm.g.Bh, tid);

    __syncthreads();

#pragma unroll
    for (int mi = 0; mi < 2; ++mi)
#pragma unroll
        for (int nj = 0; nj < 4; ++nj) {
            int row = warpM * 32 + mi * 16 + grp;
            int col = warpN * 32 + nj * 8 + 2 * qd;
            *(float2*)&sm.e.Kp[row * 64 + col] =
                make_float2(cs[mi][nj][0], cs[mi][nj][1]);
            *(float2*)&sm.e.Kp[(row + 8) * 64 + col] =
                make_float2(cs[mi][nj][2], cs[mi][nj][3]);
        }
    {
        const float* qsrc = g_qT + (size_t)bh * ND * NG;
#pragma unroll
        for (int r = 0; r < 4; ++r) {
            int off = (tid + 256 * r) * 4;
            *(float4*)&sm.e.Qs[off] = *(const float4*)&qsrc[off];
        }
    }
    __syncthreads();

    float qmax = sqrtf(g_qmax[bh]);

    int tr = tid >> 4, tc = tid & 15;
    float acc2[8][4] = {};
    float akk[8] = {};
#pragma unroll 8
    for (int d = 0; d < 64; ++d) {
        float4 q4 = *(const float4*)&sm.e.Qs[d * 64 + tc * 4];
#pragma unroll
        for (int i = 0; i < 8; ++i) {
            float a = sm.e.Kp[(tr * 8 + i) * 64 + d];
            acc2[i][0] += a * q4.x;
            acc2[i][1] += a * q4.y;
            acc2[i][2] += a * q4.z;
            acc2[i][3] += a * q4.w;
            akk[i] += a * a;
        }
    }
#pragma unroll
    for (int i = 0; i < 8; ++i) {
        float m1 = acc2[i][0], m2 = -3.4e38f;
        int i1 = tc * 4;
#pragma unroll
        for (int j = 1; j < 4; ++j) {
            float v = acc2[i][j];
            if (v > m1) { m2 = m1; m1 = v; i1 = tc * 4 + j; }
            else if (v > m2) m2 = v;
        }
#pragma unroll
        for (int off = 8; off >= 1; off >>= 1) {
            float om1 = __shfl_down_sync(0xffffffffu, m1, off, 16);
            int   oi1 = __shfl_down_sync(0xffffffffu, i1, off, 16);
            float om2 = __shfl_down_sync(0xffffffffu, m2, off, 16);
            if (om1 > m1) { m2 = fmaxf(m1, om2); m1 = om1; i1 = oi1; }
            else          { m2 = fmaxf(m2, om1); }
        }
        if (tc == 0) {
            int s = sBase + tr * 8 + i;
            g_idx[bh * NS + s] = i1;
            atomicAdd(&g_cnt[bh * NG + i1], 1);
            float T = TC * sqrtf(akk[i]) * qmax;
            if (m1 - m2 < T) {
                int p = atomicAdd(&g_fcnt[bh], 1);
                g_flag[bh * NS + p] = s;
            }
        }
    }
}

// ---------------------------------------------------------------------------
// K2b: batched fp32 recompute of flagged tokens (per-bh mini-GEMM)
// grid = (96, RSPLIT); B tile stored transposed [c][n] -> conflict-free reads
// ---------------------------------------------------------------------------
__global__ void __launch_bounds__(256) k_repair(const float* __restrict__ key,
                                                const float* __restrict__ Wk) {
    __shared__ __align__(16) union {
        struct { float A[64 * RP]; float Bt[32 * BTP]; } g;  // 9216+8704 B
        float Q[64 * 64];                                    // 16384 B
    } u;
    __shared__ __align__(16) float Kp[64 * 68];
    __shared__ int sS[64];

    int tid = threadIdx.x;
    int bh = blockIdx.x;
    int b = bh / NH, h = bh % NH;
    int nf = g_fcnt[bh];
    const float* qsrc = g_qT + (size_t)bh * ND * NG;

    int ttr = tid >> 4, ttc = tid & 15;
    int lr = tid >> 2;              // 0..63
    int cg = (tid & 3) * 8;         // 0,8,16,24
    const float* wrow = Wk + (size_t)(h * 64 + lr) * NC + cg;

    for (int c0 = blockIdx.y * 64; c0 < nf; c0 += RSPLIT * 64) {
        __syncthreads();
        if (tid < 64) {
            int i = c0 + tid;
            sS[tid] = g_flag[bh * NS + (i < nf ? i : nf - 1)];
        }
        __syncthreads();

        float acc[4][4] = {};
        const float* krow = key + ((size_t)b * NS + sS[lr]) * NC + cg;
        for (int kt = 0; kt < NC / 32; ++kt) {
            int kof = kt * 32;
            *(float4*)&u.g.A[lr * RP + cg]     = *(const float4*)(krow + kof);
            *(float4*)&u.g.A[lr * RP + cg + 4] = *(const float4*)(krow + kof + 4);
            // B transposed: Bt[c][n]
            float4 w0 = *(const float4*)(wrow + kof);
            float4 w1 = *(const float4*)(wrow + kof + 4);
            u.g.Bt[(cg + 0) * BTP + lr] = w0.x;
            u.g.Bt[(cg + 1) * BTP + lr] = w0.y;
            u.g.Bt[(cg + 2) * BTP + lr] = w0.z;
            u.g.Bt[(cg + 3) * BTP + lr] = w0.w;
            u.g.Bt[(cg + 4) * BTP + lr] = w1.x;
            u.g.Bt[(cg + 5) * BTP + lr] = w1.y;
            u.g.Bt[(cg + 6) * BTP + lr] = w1.z;
            u.g.Bt[(cg + 7) * BTP + lr] = w1.w;
            __syncthreads();
#pragma unroll 8
            for (int c = 0; c < 32; ++c) {
                float a[4];
#pragma unroll
                for (int i = 0; i < 4; ++i) a[i] = u.g.A[(ttr * 4 + i) * RP + c];
                float4 b4 = *(const float4*)&u.g.Bt[c * BTP + ttc * 4];
                float bb[4] = {b4.x, b4.y, b4.z, b4.w};
#pragma unroll
                for (int i = 0; i < 4; ++i)
#pragma unroll
                    for (int j = 0; j < 4; ++j)
                        acc[i][j] += a[i] * bb[j];
            }
            __syncthreads();
        }
        // kp -> smem, then q tile (overwrites A/B)
#pragma unroll
        for (int i = 0; i < 4; ++i)
#pragma unroll
            for (int j = 0; j < 4; ++j)
                Kp[(ttr * 4 + i) * 68 + ttc * 4 + j] = acc[i][j];
#pragma unroll
        for (int r = 0; r < 4; ++r) {
            int off = (tid + 256 * r) * 4;
            *(float4*)&u.Q[off] = *(const float4*)&qsrc[off];
        }
        __syncthreads();

        // fp32 scores + argmax (reference association: dot over d ascending)
        float s2[4][4] = {};
#pragma unroll 8
        for (int d = 0; d < 64; ++d) {
            float4 q4 = *(const float4*)&u.Q[d * 64 + ttc * 4];
#pragma unroll
            for (int i = 0; i < 4; ++i) {
                float a = Kp[(ttr * 4 + i) * 68 + d];
                s2[i][0] += a * q4.x;
                s2[i][1] += a * q4.y;
                s2[i][2] += a * q4.z;
                s2[i][3] += a * q4.w;
            }
        }
#pragma unroll
        for (int i = 0; i < 4; ++i) {
            float mv = s2[i][0];
            int mi = ttc * 4;
#pragma unroll
            for (int j = 1; j < 4; ++j)
                if (s2[i][j] > mv) { mv = s2[i][j]; mi = ttc * 4 + j; }
#pragma unroll
            for (int off = 8; off >= 1; off >>= 1) {
                float ov = __shfl_down_sync(0xffffffffu, mv, off, 16);
                int   oi = __shfl_down_sync(0xffffffffu, mi, off, 16);
                if (ov > mv || (ov == mv && oi < mi)) { mv = ov; mi = oi; }
            }
            int row = ttr * 4 + i;
            if (ttc == 0 && c0 + row < nf) {
                int s = sS[row];
                int old = g_idx[bh * NS + s];
                if (old != mi) {
                    g_idx[bh * NS + s] = mi;
                    atomicAdd(&g_cnt[bh * NG + old], -1);
                    atomicAdd(&g_cnt[bh * NG + mi], 1);
                }
            }
        }
    }
}

// ---------------------------------------------------------------------------
// K3: vp = key@Wv^T via 1xTF32 + fused atomic scatter (R3-identical)
// ---------------------------------------------------------------------------
__global__ void __launch_bounds__(256) k3_scatter(const float* __restrict__ key,
                                                  const float* __restrict__ Wv) {
    __shared__ __align__(16) float Ah[128 * PA];
    __shared__ __align__(16) float Bvh[64 * PA];

    int tid = threadIdx.x;
    int lane = tid & 31;
    int warpM = (tid >> 5) & 3, warpN = tid >> 7;
    int grp = lane >> 2, qd = lane & 3;

    int mBase = blockIdx.x * 128;
    int b = mBase >> 12;
    int sBase = mBase & (NS - 1);
    int h = blockIdx.y;
    int bh = b * NH + h;

    float cv[2][4][4] = {};
    gemm_tf32_1x(key, Wv + (size_t)h * 64 * NC, mBase, cv, Ah, Bvh, tid);

#pragma unroll
    for (int mi = 0; mi < 2; ++mi) {
        int s0 = sBase + warpM * 32 + mi * 16 + grp;
        int n0 = g_idx[bh * NS + s0];
        int n1 = g_idx[bh * NS + s0 + 8];
#pragma unroll
        for (int nj = 0; nj < 4; ++nj) {
            int d = warpN * 32 + nj * 8 + 2 * qd;
            float* p0 = &g_acc[(bh * NG + n0) * ND + d];
            atomicAdd(p0,     cv[mi][nj][0]);
            atomicAdd(p0 + 1, cv[mi][nj][1]);
            float* p1 = &g_acc[(bh * NG + n1) * ND + d];
            atomicAdd(p1,     cv[mi][nj][2]);
            atomicAdd(p1 + 1, cv[mi][nj][3]);
        }
    }
}

// ---------------------------------------------------------------------------
// K4: normalize + out = tmp @ Wp^T + bp
// ---------------------------------------------------------------------------
__global__ void __launch_bounds__(256) k_finalize(const float* __restrict__ Wp,
                                                  const float* __restrict__ bp,
                                                  float* __restrict__ out) {
    __shared__ float As[BK * AP];
    __shared__ float Bs[BK * BP2];
    int tid = threadIdx.x;
    int trow = tid >> 4, tcol = tid & 15;
    int mBase = blockIdx.x * BM;
    int nBase = blockIdx.y * BN;

    float c[8][4] = {};
    for (int k0 = 0; k0 < NC; k0 += BK) {
#pragma unroll
        for (int l = 0; l < 2; ++l) {
            int lin = tid * 2 + l;
            int m = lin >> 2;
            int kg = (lin & 3) * 4;
            int gm = mBase + m;
            int b = gm >> 6, n = gm & 63;
            int cc = k0 + kg;
            int h = cc >> 6, d = cc & 63;
            int bh = b * NH + h;
            float inv = 1.0f / (float)(g_cnt[bh * NG + n] + 1);
            float4 v = *(const float4*)&g_acc[(bh * NG + n) * ND + d];
            As[(kg + 0) * AP + m] = v.x * inv;
            As[(kg + 1) * AP + m] = v.y * inv;
            As[(kg + 2) * AP + m] = v.z * inv;
            As[(kg + 3) * AP + m] = v.w * inv;
        }
        load_B_tile(Wp, nBase, k0, Bs, tid);
        __syncthreads();
        mma_tile(As, Bs, c, trow, tcol);
        __syncthreads();
    }

    float4 bias = *(const float4*)&bp[nBase + tcol * 4];
#pragma unroll
    for (int i = 0; i < 8; ++i) {
        int m = mBase + trow * 8 + i;
        float4 v = make_float4(c[i][0] + bias.x, c[i][1] + bias.y,
                               c[i][2] + bias.z, c[i][3] + bias.w);
        *(float4*)&out[(size_t)m * NC + nBase + tcol * 4] = v;
    }
}

// ---------------------------------------------------------------------------
extern "C" void kernel_launch(void* const* d_in, const int* in_sizes, int n_in,
                              void* d_out, int out_size) {
    const float* query = (const float*)d_in[0];
    const float* key   = (const float*)d_in[1];
    const float* Wq    = (const float*)d_in[2];
    const float* Wk    = (const float*)d_in[3];
    const float* Wv    = (const float*)d_in[4];
    const float* Wp    = (const float*)d_in[5];
    const float* bp    = (const float*)d_in[6];
    float* out = (float*)d_out;

    k_zero<<<(NB * NH * NG * ND + 255) / 256, 256>>>();
    k_qproj<<<dim3(8, 6), 256>>>(query, Wq);
    k2_assign<<<dim3((NB * NS) / 128, NH), 256>>>(key, Wk);
    k_repair<<<dim3(NB * NH, RSPLIT), 256>>>(key, Wk);
    k3_scatter<<<dim3((NB * NS) / 128, NH), 256>>>(key, Wv);
    k_finalize<<<dim3(8, 6), 256>>>(Wp, bp, out);
}

// round 17
// speedup vs baseline: 2.7114x; 1.1589x over previous
#include <cuda_runtime.h>
#include <cstdint>

// Problem constants
#define NB 16
#define NG 64
#define NS 4096
#define NC 384
#define NH 6
#define ND 64

// fp32 helper-GEMM tile config (K1/K4, small)
#define BM 128
#define BN 64
#define BK 16
#define AP 132
#define BP2 68

// tf32 GEMM smem pitch
#define PA 20

// repair GEMM pitches
#define RP 36
#define BTP 68
#define RSPLIT 32

// flag threshold coefficient
#define TC 6.0e-4f

// fused kernel dynamic smem layout (bytes)
#define F_AH 0
#define F_BK 10240
#define F_BV 15360
#define F_KP 0
#define F_QS 32768
#define F_SMEM 49152

// Scratch
__device__ __align__(16) float g_qT[NB * NH * ND * NG];   // q^T: [bh][d][n]
__device__ int   g_idx[NB * NH * NS];
__device__ __align__(16) float g_acc[NB * NH * NG * ND];
__device__ int   g_cnt[NB * NH * NG];
__device__ float g_qmax[NB * NH];
__device__ int   g_fcnt[NB * NH];
__device__ int   g_flag[NB * NH * NS];
__device__ __align__(16) float g_vp[(size_t)NB * NH * NS * ND];  // flagged rows only

// ---------------------------------------------------------------------------
// tf32 helpers
// ---------------------------------------------------------------------------
__device__ __forceinline__ uint32_t f2tf(float x) {
    uint32_t u;
    asm("cvt.rna.tf32.f32 %0, %1;" : "=r"(u) : "f"(x));
    return u;
}

__device__ __forceinline__ void mma_tf32(float c[4], const uint32_t a[4],
                                         const uint32_t b[2]) {
    asm volatile(
        "mma.sync.aligned.m16n8k8.row.col.f32.tf32.tf32.f32 "
        "{%0,%1,%2,%3}, {%4,%5,%6,%7}, {%8,%9}, {%0,%1,%2,%3};"
        : "+f"(c[0]), "+f"(c[1]), "+f"(c[2]), "+f"(c[3])
        : "r"(a[0]), "r"(a[1]), "r"(a[2]), "r"(a[3]), "r"(b[0]), "r"(b[1]));
}

__device__ __forceinline__ void sts_cvt(float* hi, int off, float4 v) {
    hi[off + 0] = __uint_as_float(f2tf(v.x));
    hi[off + 1] = __uint_as_float(f2tf(v.y));
    hi[off + 2] = __uint_as_float(f2tf(v.z));
    hi[off + 3] = __uint_as_float(f2tf(v.w));
}

// ---------------------------------------------------------------------------
// fp32 helper GEMM pieces (K1 / K4)
// ---------------------------------------------------------------------------
__device__ __forceinline__ void load_A_tile(const float* __restrict__ A,
                                            int mBase, int k0, float* As, int tid) {
#pragma unroll
    for (int l = 0; l < 2; ++l) {
        int lin = tid * 2 + l;
        int m = lin >> 2;
        int kg = (lin & 3) * 4;
        float4 v = *(const float4*)(A + (size_t)(mBase + m) * NC + k0 + kg);
        As[(kg + 0) * AP + m] = v.x;
        As[(kg + 1) * AP + m] = v.y;
        As[(kg + 2) * AP + m] = v.z;
        As[(kg + 3) * AP + m] = v.w;
    }
}

__device__ __forceinline__ void load_B_tile(const float* __restrict__ W,
                                            int nBase, int k0, float* Bs, int tid) {
    int wr = tid >> 2;
    int kg = (tid & 3) * 4;
    float4 v = *(const float4*)(W + (size_t)(nBase + wr) * NC + k0 + kg);
    Bs[(kg + 0) * BP2 + wr] = v.x;
    Bs[(kg + 1) * BP2 + wr] = v.y;
    Bs[(kg + 2) * BP2 + wr] = v.z;
    Bs[(kg + 3) * BP2 + wr] = v.w;
}

__device__ __forceinline__ void mma_tile(const float* As, const float* Bs,
                                         float c[8][4], int trow, int tcol) {
#pragma unroll
    for (int k = 0; k < BK; ++k) {
        float4 a0 = *(const float4*)(As + k * AP + trow * 8);
        float4 a1 = *(const float4*)(As + k * AP + trow * 8 + 4);
        float4 b0 = *(const float4*)(Bs + k * BP2 + tcol * 4);
        float a[8] = {a0.x, a0.y, a0.z, a0.w, a1.x, a1.y, a1.z, a1.w};
        float b[4] = {b0.x, b0.y, b0.z, b0.w};
#pragma unroll
        for (int i = 0; i < 8; ++i)
#pragma unroll
            for (int j = 0; j < 4; ++j)
                c[i][j] += a[i] * b[j];
    }
}

// ---------------------------------------------------------------------------
// K0: zero accumulators + flag state
// ---------------------------------------------------------------------------
__global__ void k_zero() {
    int i = blockIdx.x * blockDim.x + threadIdx.x;
    if (i < NB * NH * NG * ND) g_acc[i] = 0.0f;
    if (i < NB * NH * NG) g_cnt[i] = 0;
    if (i < NB * NH) { g_qmax[i] = 0.0f; g_fcnt[i] = 0; }
}

// ---------------------------------------------------------------------------
// K1: q projection -> g_qT[bh][d][n], plus per-bh max ||q_n||^2
// ---------------------------------------------------------------------------
__global__ void __launch_bounds__(256) k_qproj(const float* __restrict__ query,
                                               const float* __restrict__ Wq) {
    __shared__ float As[BK * AP];
    __shared__ float Bs[BK * BP2];
    int tid = threadIdx.x;
    int trow = tid >> 4, tcol = tid & 15;
    int mBase = blockIdx.x * BM;
    int h = blockIdx.y;

    float c[8][4] = {};
    for (int k0 = 0; k0 < NC; k0 += BK) {
        load_A_tile(query, mBase, k0, As, tid);
        load_B_tile(Wq, h * 64, k0, Bs, tid);
        __syncthreads();
        mma_tile(As, Bs, c, trow, tcol);
        __syncthreads();
    }
#pragma unroll
    for (int i = 0; i < 8; ++i) {
        int m = mBase + trow * 8 + i;
        int b = m >> 6, n = m & 63;
        int bh = b * NH + h;
        float qn2 = 0.0f;
#pragma unroll
        for (int j = 0; j < 4; ++j) {
            int d = tcol * 4 + j;
            g_qT[((size_t)bh * ND + d) * NG + n] = c[i][j];
            qn2 += c[i][j] * c[i][j];
        }
#pragma unroll
        for (int off = 8; off >= 1; off >>= 1)
            qn2 += __shfl_xor_sync(0xffffffffu, qn2, off, 16);
        if (tcol == 0)
            atomicMax((unsigned int*)&g_qmax[bh], __float_as_uint(qn2));
    }
}

// ---------------------------------------------------------------------------
// K23 fused: kp = key@Wk^T AND vp = key@Wv^T (both 1xTF32) in one A pass.
// Epilogue: fp32 scores + argmax + flags (identical math to R16 k2), then
// scatter vp with preliminary idx; flagged rows also backed up to g_vp so
// repair can move contributions exactly.
// ---------------------------------------------------------------------------
__global__ void __launch_bounds__(256) k23_fused(const float* __restrict__ key,
                                                 const float* __restrict__ Wk,
                                                 const float* __restrict__ Wv) {
    extern __shared__ char dsm[];
    __shared__ int sIdx[128];
    __shared__ int sFlag[128];

    float* Ah  = (float*)(dsm + F_AH);
    float* Bkh = (float*)(dsm + F_BK);
    float* Bvh = (float*)(dsm + F_BV);

    int tid = threadIdx.x;
    int lane = tid & 31;
    int warpM = (tid >> 5) & 3, warpN = tid >> 7;
    int grp = lane >> 2, qd = lane & 3;

    int mBase = blockIdx.x * 128;
    int b = mBase >> 12;
    int sBase = mBase & (NS - 1);
    int h = blockIdx.y;
    int bh = b * NH + h;

    const float* WkH = Wk + (size_t)h * 64 * NC;
    const float* WvH = Wv + (size_t)h * 64 * NC;

    float cs[2][4][4] = {};
    float cv[2][4][4] = {};

    int am0 = tid >> 2;
    int ak = (tid & 3) * 4;
    const float* pa0 = key + (size_t)(mBase + am0) * NC + ak;
    const float* pa1 = pa0 + (size_t)64 * NC;
    const float* pbk = WkH + (size_t)am0 * NC + ak;
    const float* pbv = WvH + (size_t)am0 * NC + ak;

    float4 ra0 = *(const float4*)pa0;
    float4 ra1 = *(const float4*)pa1;
    float4 rbk = *(const float4*)pbk;
    float4 rbv = *(const float4*)pbv;

    for (int kt = 0; kt < NC / 16; ++kt) {
        __syncthreads();
        sts_cvt(Ah,  am0 * PA + ak, ra0);
        sts_cvt(Ah,  (am0 + 64) * PA + ak, ra1);
        sts_cvt(Bkh, am0 * PA + ak, rbk);
        sts_cvt(Bvh, am0 * PA + ak, rbv);
        __syncthreads();
        if (kt < NC / 16 - 1) {
            int k0 = (kt + 1) * 16;
            ra0 = *(const float4*)(pa0 + k0);
            ra1 = *(const float4*)(pa1 + k0);
            rbk = *(const float4*)(pbk + k0);
            rbv = *(const float4*)(pbv + k0);
        }
#pragma unroll
        for (int kk = 0; kk < 16; kk += 8) {
            uint32_t ah[2][4], bk[4][2], bv[4][2];
#pragma unroll
            for (int mi = 0; mi < 2; ++mi) {
                int r = warpM * 32 + mi * 16 + grp;
                const float* ph = Ah + r * PA + kk + qd;
                ah[mi][0] = __float_as_uint(ph[0]);
                ah[mi][1] = __float_as_uint(ph[8 * PA]);
                ah[mi][2] = __float_as_uint(ph[4]);
                ah[mi][3] = __float_as_uint(ph[8 * PA + 4]);
            }
#pragma unroll
            for (int nj = 0; nj < 4; ++nj) {
                int cn = warpN * 32 + nj * 8 + grp;
                const float* pk = Bkh + cn * PA + kk + qd;
                const float* pv = Bvh + cn * PA + kk + qd;
                bk[nj][0] = __float_as_uint(pk[0]);
                bk[nj][1] = __float_as_uint(pk[4]);
                bv[nj][0] = __float_as_uint(pv[0]);
                bv[nj][1] = __float_as_uint(pv[4]);
            }
#pragma unroll
            for (int mi = 0; mi < 2; ++mi)
#pragma unroll
                for (int nj = 0; nj < 4; ++nj) {
                    mma_tf32(cs[mi][nj], ah[mi], bk[nj]);
                    mma_tf32(cv[mi][nj], ah[mi], bv[nj]);
                }
        }
    }

    __syncthreads();  // GEMM smem reads done before union repurpose

    float* Kp = (float*)(dsm + F_KP);
    float* Qs = (float*)(dsm + F_QS);

    // Stage kp accumulators to smem [s][d]
#pragma unroll
    for (int mi = 0; mi < 2; ++mi)
#pragma unroll
        for (int nj = 0; nj < 4; ++nj) {
            int row = warpM * 32 + mi * 16 + grp;
            int col = warpN * 32 + nj * 8 + 2 * qd;
            *(float2*)&Kp[row * 64 + col] =
                make_float2(cs[mi][nj][0], cs[mi][nj][1]);
            *(float2*)&Kp[(row + 8) * 64 + col] =
                make_float2(cs[mi][nj][2], cs[mi][nj][3]);
        }
    {
        const float* qsrc = g_qT + (size_t)bh * ND * NG;
#pragma unroll
        for (int r = 0; r < 4; ++r) {
            int off = (tid + 256 * r) * 4;
            *(float4*)&Qs[off] = *(const float4*)&qsrc[off];
        }
    }
    __syncthreads();

    float qmax = sqrtf(g_qmax[bh]);

    int tr = tid >> 4, tc = tid & 15;
    float acc2[8][4] = {};
    float akk[8] = {};
#pragma unroll 8
    for (int d = 0; d < 64; ++d) {
        float4 q4 = *(const float4*)&Qs[d * 64 + tc * 4];
#pragma unroll
        for (int i = 0; i < 8; ++i) {
            float a = Kp[(tr * 8 + i) * 64 + d];
            acc2[i][0] += a * q4.x;
            acc2[i][1] += a * q4.y;
            acc2[i][2] += a * q4.z;
            acc2[i][3] += a * q4.w;
            akk[i] += a * a;
        }
    }
#pragma unroll
    for (int i = 0; i < 8; ++i) {
        float m1 = acc2[i][0], m2 = -3.4e38f;
        int i1 = tc * 4;
#pragma unroll
        for (int j = 1; j < 4; ++j) {
            float v = acc2[i][j];
            if (v > m1) { m2 = m1; m1 = v; i1 = tc * 4 + j; }
            else if (v > m2) m2 = v;
        }
#pragma unroll
        for (int off = 8; off >= 1; off >>= 1) {
            float om1 = __shfl_down_sync(0xffffffffu, m1, off, 16);
            int   oi1 = __shfl_down_sync(0xffffffffu, i1, off, 16);
            float om2 = __shfl_down_sync(0xffffffffu, m2, off, 16);
            if (om1 > m1) { m2 = fmaxf(m1, om2); m1 = om1; i1 = oi1; }
            else          { m2 = fmaxf(m2, om1); }
        }
        if (tc == 0) {
            int row = tr * 8 + i;
            int s = sBase + row;
            g_idx[bh * NS + s] = i1;
            sIdx[row] = i1;
            atomicAdd(&g_cnt[bh * NG + i1], 1);
            float T = TC * sqrtf(akk[i]) * qmax;
            int fl = (m1 - m2 < T) ? 1 : 0;
            sFlag[row] = fl;
            if (fl) {
                int p = atomicAdd(&g_fcnt[bh], 1);
                g_flag[bh * NS + p] = s;
            }
        }
    }
    __syncthreads();

    // scatter vp with preliminary idx; back up flagged rows to g_vp
#pragma unroll
    for (int mi = 0; mi < 2; ++mi) {
        int r0 = warpM * 32 + mi * 16 + grp;
        int n0 = sIdx[r0], n1 = sIdx[r0 + 8];
        int f0 = sFlag[r0], f1 = sFlag[r0 + 8];
        size_t t0 = ((size_t)bh * NS + sBase + r0) * ND;
        size_t t1 = t0 + (size_t)8 * ND;
#pragma unroll
        for (int nj = 0; nj < 4; ++nj) {
            int d = warpN * 32 + nj * 8 + 2 * qd;
            float* p0 = &g_acc[(bh * NG + n0) * ND + d];
            atomicAdd(p0,     cv[mi][nj][0]);
            atomicAdd(p0 + 1, cv[mi][nj][1]);
            if (f0) *(float2*)&g_vp[t0 + d] =
                make_float2(cv[mi][nj][0], cv[mi][nj][1]);
            float* p1 = &g_acc[(bh * NG + n1) * ND + d];
            atomicAdd(p1,     cv[mi][nj][2]);
            atomicAdd(p1 + 1, cv[mi][nj][3]);
            if (f1) *(float2*)&g_vp[t1 + d] =
                make_float2(cv[mi][nj][2], cv[mi][nj][3]);
        }
    }
}

// ---------------------------------------------------------------------------
// K2b: batched fp32 recompute of flagged tokens; fixes idx, cnt AND moves
// the exact scattered vp contribution for changed tokens.
// ---------------------------------------------------------------------------
__global__ void __launch_bounds__(256) k_repair(const float* __restrict__ key,
                                                const float* __restrict__ Wk) {
    __shared__ __align__(16) union {
        struct { float A[64 * RP]; float Bt[32 * BTP]; } g;
        float Q[64 * 64];
    } u;
    __shared__ __align__(16) float Kp[64 * 68];
    __shared__ int sS[64];
    __shared__ int sNchg;
    __shared__ int sChgS[64], sChgOld[64], sChgNew[64];

    int tid = threadIdx.x;
    int bh = blockIdx.x;
    int b = bh / NH, h = bh % NH;
    int nf = g_fcnt[bh];
    const float* qsrc = g_qT + (size_t)bh * ND * NG;

    int ttr = tid >> 4, ttc = tid & 15;
    int lr = tid >> 2;
    int cg = (tid & 3) * 8;
    const float* wrow = Wk + (size_t)(h * 64 + lr) * NC + cg;

    for (int c0 = blockIdx.y * 64; c0 < nf; c0 += RSPLIT * 64) {
        __syncthreads();
        if (tid == 0) sNchg = 0;
        if (tid < 64) {
            int i = c0 + tid;
            sS[tid] = g_flag[bh * NS + (i < nf ? i : nf - 1)];
        }
        __syncthreads();

        float acc[4][4] = {};
        const float* krow = key + ((size_t)b * NS + sS[lr]) * NC + cg;
        for (int kt = 0; kt < NC / 32; ++kt) {
            int kof = kt * 32;
            *(float4*)&u.g.A[lr * RP + cg]     = *(const float4*)(krow + kof);
            *(float4*)&u.g.A[lr * RP + cg + 4] = *(const float4*)(krow + kof + 4);
            float4 w0 = *(const float4*)(wrow + kof);
            float4 w1 = *(const float4*)(wrow + kof + 4);
            u.g.Bt[(cg + 0) * BTP + lr] = w0.x;
            u.g.Bt[(cg + 1) * BTP + lr] = w0.y;
            u.g.Bt[(cg + 2) * BTP + lr] = w0.z;
            u.g.Bt[(cg + 3) * BTP + lr] = w0.w;
            u.g.Bt[(cg + 4) * BTP + lr] = w1.x;
            u.g.Bt[(cg + 5) * BTP + lr] = w1.y;
            u.g.Bt[(cg + 6) * BTP + lr] = w1.z;
            u.g.Bt[(cg + 7) * BTP + lr] = w1.w;
            __syncthreads();
#pragma unroll 8
            for (int c = 0; c < 32; ++c) {
                float a[4];
#pragma unroll
                for (int i = 0; i < 4; ++i) a[i] = u.g.A[(ttr * 4 + i) * RP + c];
                float4 b4 = *(const float4*)&u.g.Bt[c * BTP + ttc * 4];
                float bb[4] = {b4.x, b4.y, b4.z, b4.w};
#pragma unroll
                for (int i = 0; i < 4; ++i)
#pragma unroll
                    for (int j = 0; j < 4; ++j)
                        acc[i][j] += a[i] * bb[j];
            }
            __syncthreads();
        }
#pragma unroll
        for (int i = 0; i < 4; ++i)
#pragma unroll
            for (int j = 0; j < 4; ++j)
                Kp[(ttr * 4 + i) * 68 + ttc * 4 + j] = acc[i][j];
#pragma unroll
        for (int r = 0; r < 4; ++r) {
            int off = (tid + 256 * r) * 4;
            *(float4*)&u.Q[off] = *(const float4*)&qsrc[off];
        }
        __syncthreads();

        float s2[4][4] = {};
#pragma unroll 8
        for (int d = 0; d < 64; ++d) {
            float4 q4 = *(const float4*)&u.Q[d * 64 + ttc * 4];
#pragma unroll
            for (int i = 0; i < 4; ++i) {
                float a = Kp[(ttr * 4 + i) * 68 + d];
                s2[i][0] += a * q4.x;
                s2[i][1] += a * q4.y;
                s2[i][2] += a * q4.z;
                s2[i][3] += a * q4.w;
            }
        }
#pragma unroll
        for (int i = 0; i < 4; ++i) {
            float mv = s2[i][0];
            int mi = ttc * 4;
#pragma unroll
            for (int j = 1; j < 4; ++j)
                if (s2[i][j] > mv) { mv = s2[i][j]; mi = ttc * 4 + j; }
#pragma unroll
            for (int off = 8; off >= 1; off >>= 1) {
                float ov = __shfl_down_sync(0xffffffffu, mv, off, 16);
                int   oi = __shfl_down_sync(0xffffffffu, mi, off, 16);
                if (ov > mv || (ov == mv && oi < mi)) { mv = ov; mi = oi; }
            }
            int row = ttr * 4 + i;
            if (ttc == 0 && c0 + row < nf) {
                int s = sS[row];
                int old = g_idx[bh * NS + s];
                if (old != mi) {
                    g_idx[bh * NS + s] = mi;
                    atomicAdd(&g_cnt[bh * NG + old], -1);
                    atomicAdd(&g_cnt[bh * NG + mi], 1);
                    int p = atomicAdd(&sNchg, 1);
                    sChgS[p] = s;
                    sChgOld[p] = old;
                    sChgNew[p] = mi;
                }
            }
        }
        __syncthreads();

        // move exact vp contribution for changed tokens
        int nchg = sNchg;
        for (int ic = 0; ic < nchg; ++ic) {
            if (tid < 64) {
                int s = sChgS[ic];
                float v = g_vp[((size_t)bh * NS + s) * ND + tid];
                atomicAdd(&g_acc[(bh * NG + sChgOld[ic]) * ND + tid], -v);
                atomicAdd(&g_acc[(bh * NG + sChgNew[ic]) * ND + tid],  v);
            }
        }
    }
}

// ---------------------------------------------------------------------------
// K4: normalize + out = tmp @ Wp^T + bp
// ---------------------------------------------------------------------------
__global__ void __launch_bounds__(256) k_finalize(const float* __restrict__ Wp,
                                                  const float* __restrict__ bp,
                                                  float* __restrict__ out) {
    __shared__ float As[BK * AP];
    __shared__ float Bs[BK * BP2];
    int tid = threadIdx.x;
    int trow = tid >> 4, tcol = tid & 15;
    int mBase = blockIdx.x * BM;
    int nBase = blockIdx.y * BN;

    float c[8][4] = {};
    for (int k0 = 0; k0 < NC; k0 += BK) {
#pragma unroll
        for (int l = 0; l < 2; ++l) {
            int lin = tid * 2 + l;
            int m = lin >> 2;
            int kg = (lin & 3) * 4;
            int gm = mBase + m;
            int b = gm >> 6, n = gm & 63;
            int cc = k0 + kg;
            int h = cc >> 6, d = cc & 63;
            int bh = b * NH + h;
            float inv = 1.0f / (float)(g_cnt[bh * NG + n] + 1);
            float4 v = *(const float4*)&g_acc[(bh * NG + n) * ND + d];
            As[(kg + 0) * AP + m] = v.x * inv;
            As[(kg + 1) * AP + m] = v.y * inv;
            As[(kg + 2) * AP + m] = v.z * inv;
            As[(kg + 3) * AP + m] = v.w * inv;
        }
        load_B_tile(Wp, nBase, k0, Bs, tid);
        __syncthreads();
        mma_tile(As, Bs, c, trow, tcol);
        __syncthreads();
    }

    float4 bias = *(const float4*)&bp[nBase + tcol * 4];
#pragma unroll
    for (int i = 0; i < 8; ++i) {
        int m = mBase + trow * 8 + i;
        float4 v = make_float4(c[i][0] + bias.x, c[i][1] + bias.y,
                               c[i][2] + bias.z, c[i][3] + bias.w);
        *(float4*)&out[(size_t)m * NC + nBase + tcol * 4] = v;
    }
}

// ---------------------------------------------------------------------------
extern "C" void kernel_launch(void* const* d_in, const int* in_sizes, int n_in,
                              void* d_out, int out_size) {
    const float* query = (const float*)d_in[0];
    const float* key   = (const float*)d_in[1];
    const float* Wq    = (const float*)d_in[2];
    const float* Wk    = (const float*)d_in[3];
    const float* Wv    = (const float*)d_in[4];
    const float* Wp    = (const float*)d_in[5];
    const float* bp    = (const float*)d_in[6];
    float* out = (float*)d_out;

    static bool attr_set = false;
    if (!attr_set) {
        cudaFuncSetAttribute(k23_fused,
                             cudaFuncAttributeMaxDynamicSharedMemorySize,
                             F_SMEM);
        attr_set = true;
    }

    k_zero<<<(NB * NH * NG * ND + 255) / 256, 256>>>();
    k_qproj<<<dim3(8, 6), 256>>>(query, Wq);
    k23_fused<<<dim3((NB * NS) / 128, NH), 256, F_SMEM>>>(key, Wk, Wv);
    k_repair<<<dim3(NB * NH, RSPLIT), 256>>>(key, Wk);
    k_finalize<<<dim3(8, 6), 256>>>(Wp, bp, out);
}